// round 14
// baseline (speedup 1.0000x reference)
#include <cuda_runtime.h>
#include <math.h>

#define BB   8
#define NN   2048
#define KNN  20
#define CLSN 40
#define EPSBN 1e-5f
#define PTS  (BB * NN)

typedef unsigned long long ull;

// ---------------- f32x2 packed-math helpers (sm_100a) ----------------
__device__ __forceinline__ ull splat2(float x) {
    unsigned u = __float_as_uint(x);
    ull r;
    asm("mov.b64 %0, {%1, %1};" : "=l"(r) : "r"(u));
    return r;
}
__device__ __forceinline__ ull pack2(float x, float y) {
    ull r;
    asm("mov.b64 %0, {%1, %2};" : "=l"(r) : "r"(__float_as_uint(x)), "r"(__float_as_uint(y)));
    return r;
}
__device__ __forceinline__ float2 unpack2(ull v) {
    unsigned lo, hi;
    asm("mov.b64 {%0, %1}, %2;" : "=r"(lo), "=r"(hi) : "l"(v));
    return make_float2(__uint_as_float(lo), __uint_as_float(hi));
}
__device__ __forceinline__ void ffma2(ull& acc, ull a, ull b) {
    asm("fma.rn.f32x2 %0, %1, %2, %0;" : "+l"(acc) : "l"(a), "l"(b));
}

// Exact order-preserving 64-bit key: high32 = monotone float bits (FULL precision),
// low32 = ~m  -> unique keys; equal values order by LOWER index first (= reference).
__device__ __forceinline__ ull packkey(float v, int m) {
    unsigned u = __float_as_uint(v);
    u ^= ((unsigned)((int)u >> 31)) | 0x80000000u;
    return ((ull)u << 32) | (ull)(0xFFFFFFFFu - (unsigned)m);
}

// ---------------- scratch (static __device__ — no allocations) ----------------
__device__ float g_xx[PTS];
__device__ float g_xt3[PTS * 3];
__device__ int   g_idx[PTS * KNN];
__device__ float g_feat[2][BB * 64 * NN];              // [c][n] layout (for knn)
__device__ float g_featt[2][(size_t)PTS * 64];         // [n][c] layout (for gather)
__device__ float g_base[PTS * 64];
__device__ float g_hacc[(size_t)PTS * KNN * 64];
__device__ float g_hm[BB * 64 * NN];
__device__ float g_h2t[(size_t)PTS * 256];
__device__ float g_pmax[BB * 32 * 256];
__device__ float g_psum[BB * 32 * 256];
__device__ float g_gvec[BB * 512];

// ---------------- stage-1 norms + transpose ----------------
__global__ void xx3t_kernel(const float* __restrict__ x) {
    int t = blockIdx.x * blockDim.x + threadIdx.x;
    if (t >= PTS) return;
    int b = t / NN, n = t % NN;
    float v0 = x[(b * 3 + 0) * NN + n];
    float v1 = x[(b * 3 + 1) * NN + n];
    float v2 = x[(b * 3 + 2) * NN + n];
    g_xx[t] = v0 * v0 + v1 * v1 + v2 * v2;
    g_xt3[t * 3 + 0] = v0;
    g_xt3[t * 3 + 1] = v1;
    g_xt3[t * 3 + 2] = v2;
}

// ---------------- top-k: EXACT register-resident bubble-carry insert ---------
struct TopK {
    float v[KNN];
    int   id[KNN];
    float thr;
    __device__ __forceinline__ void init() {
#pragma unroll
        for (int i = 0; i < KNN; i++) { v[i] = -3e38f; id[i] = 0; }
        thr = -3e38f;
    }
    __device__ __forceinline__ void push(float val, int m) {
        if (val > thr) {
            float cv = val; int ci = m;
#pragma unroll
            for (int i = 0; i < KNN; i++) {
                bool sw = (cv > v[i]);
                float nv = sw ? cv : v[i];
                int   ni = sw ? ci : id[i];
                cv = sw ? v[i] : cv;
                ci = sw ? id[i] : ci;
                v[i] = nv; id[i] = ni;
            }
            thr = v[KNN - 1];
        }
    }
};

// ---------------- 4-way merge of sorted packed-key lists (exact) -------------
__device__ __forceinline__ void merge4_to(const ull* L0, const ull* L1,
                                          const ull* L2, const ull* L3, int* op) {
    int p0 = 0, p1 = 0, p2 = 0, p3 = 0;
#pragma unroll
    for (int k = 0; k < KNN; k++) {
        ull a = L0[p0], b = L1[p1], c = L2[p2], d = L3[p3];
        ull best = a; int src = 0;
        if (b > best) { best = b; src = 1; }
        if (c > best) { best = c; src = 2; }
        if (d > best) { best = d; src = 3; }
        op[k] = (int)(0xFFFFFFFFu - (unsigned)(best & 0xFFFFFFFFull));
        if (src == 0) p0++; else if (src == 1) p1++; else if (src == 2) p2++; else p3++;
    }
}

// ---------------- kNN, C=3 (stage 1): 64 queries x 4 groups ----------------
__global__ __launch_bounds__(256) void knn3_kernel(const float* __restrict__ x) {
    __shared__ __align__(16) float sm[4][NN];  // s0,s1,s2,sxx (32KB); lists g1-3 overlay
    __shared__ ull l0[64 * KNN];               // 10KB group-0 lists
    int b = blockIdx.y;
    int tid = threadIdx.x;
    int q = tid & 63, g = tid >> 6;            // warp-uniform g
    int n = blockIdx.x * 64 + q;
    for (int i = tid; i < NN; i += 256) {
        sm[0][i] = x[(b * 3 + 0) * NN + i];
        sm[1][i] = x[(b * 3 + 1) * NN + i];
        sm[2][i] = x[(b * 3 + 2) * NN + i];
        sm[3][i] = g_xx[b * NN + i];
    }
    __syncthreads();
    float q0 = sm[0][n], q1 = sm[1][n], q2 = sm[2][n], xq = sm[3][n];
    TopK tk; tk.init();
    int mbase = g * 512;
    for (int m = mbase; m < mbase + 512; m++) {
        float d = q0 * sm[0][m] + q1 * sm[1][m] + q2 * sm[2][m];
        tk.push(2.f * d - xq - sm[3][m], m);
    }
    __syncthreads();                            // all reads of sm done
    ull* lg = (g == 0) ? &l0[q * KNN] : ((ull*)sm) + ((g - 1) * 64 + q) * KNN;
#pragma unroll
    for (int k = 0; k < KNN; k++) lg[k] = packkey(tk.v[k], tk.id[k]);
    __syncthreads();
    if (tid < 64) {
        merge4_to(&l0[tid * KNN],
                  ((ull*)sm) + (0 * 64 + tid) * KNN,
                  ((ull*)sm) + (1 * 64 + tid) * KNN,
                  ((ull*)sm) + (2 * 64 + tid) * KNN,
                  g_idx + (b * NN + blockIdx.x * 64 + tid) * KNN);
    }
}

// ---------------- kNN, C=64 (stages 2-4): 64 queries x 4 groups + f32x2 ------
__global__ __launch_bounds__(256) void knn64_kernel(int sel) {
    const float* x = g_feat[sel];               // [b][64][NN]
    __shared__ __align__(16) float4 s4[4 * 512]; // 32KB; lists g1-3 overlay later
    __shared__ float sxx[4][32];
    __shared__ ull l0[64 * KNN];                // 10KB group-0 lists
    int b = blockIdx.y;
    int tid = threadIdx.x;
    int q = tid & 63, g = tid >> 6;             // warp-uniform g
    int n = blockIdx.x * 64 + q;
    float qf[64];
#pragma unroll
    for (int c = 0; c < 64; c++) qf[c] = x[(b * 64 + c) * NN + n];
    float xq = g_xx[b * NN + n];
    TopK tk; tk.init();
    int mbase = g * 512;
    float4* sg = s4 + g * 512;
    for (int m0 = 0; m0 < 512; m0 += 32) {
        __syncthreads();
        for (int i = q; i < 512; i += 64) {     // 512 float4 = 64 ch x 32 cands
            int c = i >> 3, j = i & 7;
            sg[i] = *(const float4*)&x[(b * 64 + c) * NN + mbase + m0 + j * 4];
        }
        if (q < 32) sxx[g][q] = g_xx[b * NN + mbase + m0 + q];
        __syncthreads();
        for (int j8 = 0; j8 < 4; j8++) {        // 8 candidates per iteration
            ull d01 = 0, d23 = 0, d45 = 0, d67 = 0;
#pragma unroll
            for (int c = 0; c < 64; c++) {      // FULL unroll: qf stays in regs
                ull q2 = splat2(qf[c]);
                ulonglong2 va = *(const ulonglong2*)&sg[c * 8 + j8 * 2];
                ulonglong2 vb = *(const ulonglong2*)&sg[c * 8 + j8 * 2 + 1];
                ffma2(d01, q2, va.x); ffma2(d23, q2, va.y);
                ffma2(d45, q2, vb.x); ffma2(d67, q2, vb.y);
            }
            int m = mbase + m0 + j8 * 8;
            int jb = j8 * 8;
            float2 p;
            p = unpack2(d01);
            tk.push(2.f * p.x - xq - sxx[g][jb + 0], m + 0);
            tk.push(2.f * p.y - xq - sxx[g][jb + 1], m + 1);
            p = unpack2(d23);
            tk.push(2.f * p.x - xq - sxx[g][jb + 2], m + 2);
            tk.push(2.f * p.y - xq - sxx[g][jb + 3], m + 3);
            p = unpack2(d45);
            tk.push(2.f * p.x - xq - sxx[g][jb + 4], m + 4);
            tk.push(2.f * p.y - xq - sxx[g][jb + 5], m + 5);
            p = unpack2(d67);
            tk.push(2.f * p.x - xq - sxx[g][jb + 6], m + 6);
            tk.push(2.f * p.y - xq - sxx[g][jb + 7], m + 7);
        }
    }
    __syncthreads();                            // all reads of s4 done
    ull* lg = (g == 0) ? &l0[q * KNN] : ((ull*)s4) + ((g - 1) * 64 + q) * KNN;
#pragma unroll
    for (int k = 0; k < KNN; k++) lg[k] = packkey(tk.v[k], tk.id[k]);
    __syncthreads();
    if (tid < 64) {
        merge4_to(&l0[tid * KNN],
                  ((ull*)s4) + (0 * 64 + tid) * KNN,
                  ((ull*)s4) + (1 * 64 + tid) * KNN,
                  ((ull*)s4) + (2 * 64 + tid) * KNN,
                  g_idx + (b * NN + blockIdx.x * 64 + tid) * KNN);
    }
}

// ---------------- base = (Wc - Wd) @ ctr ----------------
template <int C>
__global__ __launch_bounds__(128) void base_kernel(const float* __restrict__ w, int selt) {
    __shared__ float wcd[64 * C];
    const float* xt = (C == 3) ? g_xt3 : g_featt[selt];
    int tid = threadIdx.x;
    for (int i = tid; i < 64 * C; i += 128) {
        int o = i / C, c = i - o * C;
        wcd[i] = w[o * 2 * C + C + c] - w[o * 2 * C + c];
    }
    __syncthreads();
    int p = blockIdx.x * 128 + tid;
    float xr[C];
#pragma unroll
    for (int c = 0; c < C; c++) xr[c] = xt[(size_t)p * C + c];
#pragma unroll 4
    for (int o = 0; o < 64; o++) {
        float a = 0.f;
#pragma unroll
        for (int c = 0; c < C; c++) a += wcd[o * C + c] * xr[c];
        g_base[p * 64 + o] = a;
    }
}

// ---------------- EdgeConv + fused w5-slice accumulate, f32x2 GEMMs ----------
template <int C, int ACCUM, int FINAL, int WRITEX>
__global__ __launch_bounds__(96) void edge_kernel(
    int selin,
    const float* __restrict__ w,    // [64][2C]
    const float* __restrict__ bnp,  // [4][64]
    const float* __restrict__ w5,   // [64][256]
    int w5off, int selout,
    const float* __restrict__ bnp5)
{
    __shared__ __align__(16) float sm[C * 64 + 4096 + 3 * 1280];
    __shared__ int sid[3][KNN];
    const float* xin_t = (C == 3) ? g_xt3 : g_featt[selin];
    float* xout  = g_feat[selout];
    float* xoutt = g_featt[selout];
    float* wd2 = sm;                 // [C][64]: (Wd[j][c], Wd[j+32][c])
    float* w52 = sm + C * 64;        // [64][64]: (w5[j][off+o], w5[j+32][off+o])
    int tid = threadIdx.x;
    float* wbuf = sm + C * 64 + 4096 + (tid >> 5) * 1280;

    for (int i = tid; i < C * 64; i += 96) {
        int c = i >> 6, t2 = i & 63, jj = t2 >> 1, hi = t2 & 1;
        wd2[i] = w[(jj + 32 * hi) * (2 * C) + c];
    }
    for (int i = tid; i < 4096; i += 96) {
        int o = i >> 6, t2 = i & 63, jj = t2 >> 1, hi = t2 & 1;
        w52[i] = w5[(jj + 32 * hi) * 256 + w5off + o];
    }
    __syncthreads();

    int lane = tid & 31, warp = tid >> 5;
    int* myid = sid[warp];
    float a0 = bnp[lane] * rsqrtf(bnp[192 + lane] + EPSBN);
    float c0 = bnp[64 + lane] - bnp[128 + lane] * a0;
    float a1 = bnp[32 + lane] * rsqrtf(bnp[224 + lane] + EPSBN);
    float c1 = bnp[96 + lane] - bnp[160 + lane] * a1;
    float a5l = 0.f, c5l = 0.f, a5h = 0.f, c5h = 0.f;
    if (FINAL) {
        a5l = bnp5[lane] * rsqrtf(bnp5[192 + lane] + EPSBN);
        c5l = bnp5[64 + lane] - bnp5[128 + lane] * a5l;
        a5h = bnp5[32 + lane] * rsqrtf(bnp5[224 + lane] + EPSBN);
        c5h = bnp5[96 + lane] - bnp5[160 + lane] * a5h;
    }

    for (int p = blockIdx.x * 3 + warp; p < PTS; p += gridDim.x * 3) {
        int b = p >> 11, n = p & (NN - 1);
        if (lane < KNN) myid[lane] = g_idx[p * KNN + lane];
        __syncwarp();
        if (C == 64) {
#pragma unroll
            for (int i = 0; i < 10; i++) {
                int idx = lane + i * 32;
                int k = idx >> 4, c4 = idx & 15;
                int nb = myid[k];
                float4 v = *(const float4*)&xin_t[((size_t)b * NN + nb) * 64 + c4 * 4];
                wbuf[(c4 * 4 + 0) * KNN + k] = v.x;
                wbuf[(c4 * 4 + 1) * KNN + k] = v.y;
                wbuf[(c4 * 4 + 2) * KNN + k] = v.z;
                wbuf[(c4 * 4 + 3) * KNN + k] = v.w;
            }
        } else {
            for (int t = lane; t < C * KNN; t += 32) {
                int k = t / C, c = t - k * C;
                wbuf[c * KNN + k] = xin_t[((size_t)b * NN + myid[k]) * C + c];
            }
        }
        __syncwarp();
        ull acc0p[10], acc1p[10];
        {
            ull b0 = splat2(g_base[p * 64 + lane]);
            ull b1 = splat2(g_base[p * 64 + 32 + lane]);
#pragma unroll
            for (int i = 0; i < 10; i++) { acc0p[i] = b0; acc1p[i] = b1; }
        }
#pragma unroll 8
        for (int c = 0; c < C; c++) {
            float2 wv = *(const float2*)&wd2[c * 64 + 2 * lane];
            ull wx = splat2(wv.x), wy = splat2(wv.y);
            const ulonglong2* nb2 = (const ulonglong2*)&wbuf[c * KNN];
#pragma unroll
            for (int qd = 0; qd < 5; qd++) {
                ulonglong2 v = nb2[qd];
                ffma2(acc0p[2 * qd], wx, v.x); ffma2(acc0p[2 * qd + 1], wx, v.y);
                ffma2(acc1p[2 * qd], wy, v.x); ffma2(acc1p[2 * qd + 1], wy, v.y);
            }
        }
        __syncwarp();
        float ym0 = -3e38f, ym1 = -3e38f;
#pragma unroll
        for (int i = 0; i < 10; i++) {
            float2 u0 = unpack2(acc0p[i]);
            float2 u1 = unpack2(acc1p[i]);
            float y00 = a0 * u0.x + c0; y00 = (y00 >= 0.f) ? y00 : 0.2f * y00;
            float y01 = a0 * u0.y + c0; y01 = (y01 >= 0.f) ? y01 : 0.2f * y01;
            float y10 = a1 * u1.x + c1; y10 = (y10 >= 0.f) ? y10 : 0.2f * y10;
            float y11 = a1 * u1.y + c1; y11 = (y11 >= 0.f) ? y11 : 0.2f * y11;
            ym0 = fmaxf(ym0, fmaxf(y00, y01));
            ym1 = fmaxf(ym1, fmaxf(y10, y11));
            *(ull*)&wbuf[lane * KNN + 2 * i]        = pack2(y00, y01);
            *(ull*)&wbuf[(lane + 32) * KNN + 2 * i] = pack2(y10, y11);
        }
        __syncwarp();
        ull h0p[10], h1p[10];
#pragma unroll
        for (int i = 0; i < 10; i++) { h0p[i] = 0ull; h1p[i] = 0ull; }
#pragma unroll 8
        for (int o = 0; o < 64; o++) {
            float2 wv = *(const float2*)&w52[o * 64 + 2 * lane];
            ull wx = splat2(wv.x), wy = splat2(wv.y);
            const ulonglong2* y2 = (const ulonglong2*)&wbuf[o * KNN];
#pragma unroll
            for (int qd = 0; qd < 5; qd++) {
                ulonglong2 v = y2[qd];
                ffma2(h0p[2 * qd], wx, v.x); ffma2(h0p[2 * qd + 1], wx, v.y);
                ffma2(h1p[2 * qd], wy, v.x); ffma2(h1p[2 * qd + 1], wy, v.y);
            }
        }
        float* hp = g_hacc + (size_t)p * KNN * 64;
        if (FINAL) {
            float m0 = -3e38f, m1 = -3e38f;
#pragma unroll
            for (int i = 0; i < 10; i++) {
                float2 h0 = unpack2(h0p[i]);
                float2 h1 = unpack2(h1p[i]);
                float v00 = a5l * (hp[(2 * i) * 64 + lane] + h0.x) + c5l;
                v00 = (v00 >= 0.f) ? v00 : 0.2f * v00;
                float v01 = a5l * (hp[(2 * i + 1) * 64 + lane] + h0.y) + c5l;
                v01 = (v01 >= 0.f) ? v01 : 0.2f * v01;
                float v10 = a5h * (hp[(2 * i) * 64 + 32 + lane] + h1.x) + c5h;
                v10 = (v10 >= 0.f) ? v10 : 0.2f * v10;
                float v11 = a5h * (hp[(2 * i + 1) * 64 + 32 + lane] + h1.y) + c5h;
                v11 = (v11 >= 0.f) ? v11 : 0.2f * v11;
                m0 = fmaxf(m0, fmaxf(v00, v01));
                m1 = fmaxf(m1, fmaxf(v10, v11));
            }
            g_hm[(b * 64 + lane) * NN + n]      = m0;
            g_hm[(b * 64 + 32 + lane) * NN + n] = m1;
        } else if (ACCUM) {
#pragma unroll
            for (int i = 0; i < 10; i++) {
                float2 h0 = unpack2(h0p[i]);
                float2 h1 = unpack2(h1p[i]);
                hp[(2 * i) * 64 + lane]          += h0.x;
                hp[(2 * i + 1) * 64 + lane]      += h0.y;
                hp[(2 * i) * 64 + 32 + lane]     += h1.x;
                hp[(2 * i + 1) * 64 + 32 + lane] += h1.y;
            }
        } else {
#pragma unroll
            for (int i = 0; i < 10; i++) {
                float2 h0 = unpack2(h0p[i]);
                float2 h1 = unpack2(h1p[i]);
                hp[(2 * i) * 64 + lane]          = h0.x;
                hp[(2 * i + 1) * 64 + lane]      = h0.y;
                hp[(2 * i) * 64 + 32 + lane]     = h1.x;
                hp[(2 * i + 1) * 64 + 32 + lane] = h1.y;
            }
        }
        if (WRITEX) {
            xout[(b * 64 + lane) * NN + n]      = ym0;
            xout[(b * 64 + 32 + lane) * NN + n] = ym1;
            xoutt[((size_t)b * NN + n) * 64 + lane]      = ym0;
            xoutt[((size_t)b * NN + n) * 64 + 32 + lane] = ym1;
            float xxv = ym0 * ym0 + ym1 * ym1;
#pragma unroll
            for (int off = 16; off > 0; off >>= 1)
                xxv += __shfl_xor_sync(0xffffffffu, xxv, off);
            if (lane == 0) g_xx[p] = xxv;
        }
        __syncwarp();
    }
}

// ---------------- conv6 (64 -> 256) + bn6 + lrelu ----------------
__global__ __launch_bounds__(256) void conv6_kernel(const float* __restrict__ w6,
                                                    const float* __restrict__ bnp) {
    __shared__ float sh[64 * 128];
    int b = blockIdx.y, n0 = blockIdx.x * 128;
    for (int i = threadIdx.x; i < 64 * 128; i += 256) {
        int c = i >> 7, j = i & 127;
        sh[i] = g_hm[(b * 64 + c) * NN + n0 + j];
    }
    int o2 = threadIdx.x;
    float wr[64];
#pragma unroll
    for (int o = 0; o < 64; o++) wr[o] = w6[o2 * 64 + o];
    float a = bnp[o2] * rsqrtf(bnp[768 + o2] + EPSBN);
    float cb = bnp[256 + o2] - bnp[512 + o2] * a;
    __syncthreads();
    for (int jj = 0; jj < 64; jj++) {
        float s0 = 0.f, s1 = 0.f;
#pragma unroll
        for (int o = 0; o < 64; o++) {
            float2 v = *(const float2*)&sh[o * 128 + jj * 2];
            s0 += wr[o] * v.x;
            s1 += wr[o] * v.y;
        }
        float v0 = a * s0 + cb; v0 = (v0 >= 0.f) ? v0 : 0.2f * v0;
        float v1 = a * s1 + cb; v1 = (v1 >= 0.f) ? v1 : 0.2f * v1;
        g_h2t[((size_t)b * NN + n0 + jj * 2) * 256 + o2] = v0;
        g_h2t[((size_t)b * NN + n0 + jj * 2 + 1) * 256 + o2] = v1;
    }
}

// ---------------- global max + mean over N (2-level) ----------------
__global__ void reduce1_kernel() {
    int b = blockIdx.y, s = blockIdx.x, o = threadIdx.x;
    float m = -3e38f, sum = 0.f;
#pragma unroll 8
    for (int j = 0; j < 64; j++) {
        float v = g_h2t[((size_t)b * NN + s * 64 + j) * 256 + o];
        m = fmaxf(m, v);
        sum += v;
    }
    g_pmax[(b * 32 + s) * 256 + o] = m;
    g_psum[(b * 32 + s) * 256 + o] = sum;
}
__global__ void reduce2_kernel() {
    int b = blockIdx.x, o = threadIdx.x;
    float m = -3e38f, s = 0.f;
#pragma unroll
    for (int j = 0; j < 32; j++) {
        m = fmaxf(m, g_pmax[(b * 32 + j) * 256 + o]);
        s += g_psum[(b * 32 + j) * 256 + o];
    }
    g_gvec[b * 512 + o] = m;
    g_gvec[b * 512 + 256 + o] = s * (1.0f / NN);
}

// ---------------- FC head ----------------
__global__ __launch_bounds__(256) void fc_kernel(
    const float* __restrict__ lw1, const float* __restrict__ lb1, const float* __restrict__ lbn1,
    const float* __restrict__ lw2, const float* __restrict__ lb2, const float* __restrict__ lbn2,
    const float* __restrict__ lw3, const float* __restrict__ lb3, float* __restrict__ out) {
    __shared__ float sg[512];
    __shared__ float sz[256];
    __shared__ float sz2[64];
    int b = blockIdx.x, t = threadIdx.x;
    sg[t] = g_gvec[b * 512 + t];
    sg[t + 256] = g_gvec[b * 512 + 256 + t];
    __syncthreads();
    {
        float acc = lb1[t];
#pragma unroll 8
        for (int i = 0; i < 512; i++) acc += lw1[t * 512 + i] * sg[i];
        float a = lbn1[t] * rsqrtf(lbn1[768 + t] + EPSBN);
        float cb = lbn1[256 + t] - lbn1[512 + t] * a;
        float v = a * acc + cb;
        sz[t] = (v >= 0.f) ? v : 0.01f * v;
    }
    __syncthreads();
    if (t < 64) {
        float acc = lb2[t];
#pragma unroll 8
        for (int i = 0; i < 256; i++) acc += lw2[t * 256 + i] * sz[i];
        float a = lbn2[t] * rsqrtf(lbn2[192 + t] + EPSBN);
        float cb = lbn2[64 + t] - lbn2[128 + t] * a;
        float v = a * acc + cb;
        sz2[t] = (v >= 0.f) ? v : 0.01f * v;
    }
    __syncthreads();
    if (t < CLSN) {
        float acc = lb3[t];
#pragma unroll
        for (int i = 0; i < 64; i++) acc += lw3[t * 64 + i] * sz2[i];
        out[b * CLSN + t] = acc;
    }
}

// ---------------- launch ----------------
extern "C" void kernel_launch(void* const* d_in, const int* in_sizes, int n_in,
                              void* d_out, int out_size) {
    const float* x    = (const float*)d_in[0];
    const float* w1   = (const float*)d_in[1];
    const float* bn1  = (const float*)d_in[2];
    const float* w2   = (const float*)d_in[3];
    const float* bn2  = (const float*)d_in[4];
    const float* w3   = (const float*)d_in[5];
    const float* bn3  = (const float*)d_in[6];
    const float* w4   = (const float*)d_in[7];
    const float* bn4  = (const float*)d_in[8];
    const float* w5   = (const float*)d_in[9];
    const float* bn5  = (const float*)d_in[10];
    const float* w6   = (const float*)d_in[11];
    const float* bn6  = (const float*)d_in[12];
    const float* lw1  = (const float*)d_in[13];
    const float* lb1  = (const float*)d_in[14];
    const float* lbn1 = (const float*)d_in[15];
    const float* lw2  = (const float*)d_in[16];
    const float* lb2  = (const float*)d_in[17];
    const float* lbn2 = (const float*)d_in[18];
    const float* lw3  = (const float*)d_in[19];
    const float* lb3  = (const float*)d_in[20];
    float* out = (float*)d_out;
    (void)in_sizes; (void)n_in; (void)out_size;

    dim3 knn_grid(NN / 64, BB);   // 32 x 8 = 256 blocks of 256 threads
    const int EG = 592;

    // stage 1 (input C=3)
    xx3t_kernel<<<(PTS + 255) / 256, 256>>>(x);
    knn3_kernel<<<knn_grid, 256>>>(x);
    base_kernel<3><<<PTS / 128, 128>>>(w1, 0);
    edge_kernel<3, 0, 0, 1><<<EG, 96>>>(0, w1, bn1, w5, 0, 0, nullptr);
    // stage 2
    knn64_kernel<<<knn_grid, 256>>>(0);
    base_kernel<64><<<PTS / 128, 128>>>(w2, 0);
    edge_kernel<64, 1, 0, 1><<<EG, 96>>>(0, w2, bn2, w5, 64, 1, nullptr);
    // stage 3
    knn64_kernel<<<knn_grid, 256>>>(1);
    base_kernel<64><<<PTS / 128, 128>>>(w3, 1);
    edge_kernel<64, 1, 0, 1><<<EG, 96>>>(1, w3, bn3, w5, 128, 0, nullptr);
    // stage 4 (fused bn5+lrelu+max_k)
    knn64_kernel<<<knn_grid, 256>>>(0);
    base_kernel<64><<<PTS / 128, 128>>>(w4, 0);
    edge_kernel<64, 1, 1, 0><<<EG, 96>>>(0, w4, bn4, w5, 192, 1, bn5);
    // tail
    conv6_kernel<<<dim3(NN / 128, BB), 256>>>(w6, bn6);
    reduce1_kernel<<<dim3(32, BB), 256>>>();
    reduce2_kernel<<<BB, 256>>>();
    fc_kernel<<<BB, 256>>>(lw1, lb1, lbn1, lw2, lb2, lbn2, lw3, lb3, out);
}

// round 15
// speedup vs baseline: 1.1381x; 1.1381x over previous
#include <cuda_runtime.h>
#include <math.h>

#define BB   8
#define NN   2048
#define KNN  20
#define CLSN 40
#define EPSBN 1e-5f
#define PTS  (BB * NN)

typedef unsigned long long ull;

// ---------------- f32x2 packed-math helpers (sm_100a) ----------------
__device__ __forceinline__ ull splat2(float x) {
    unsigned u = __float_as_uint(x);
    ull r;
    asm("mov.b64 %0, {%1, %1};" : "=l"(r) : "r"(u));
    return r;
}
__device__ __forceinline__ ull pack2(float x, float y) {
    ull r;
    asm("mov.b64 %0, {%1, %2};" : "=l"(r) : "r"(__float_as_uint(x)), "r"(__float_as_uint(y)));
    return r;
}
__device__ __forceinline__ float2 unpack2(ull v) {
    unsigned lo, hi;
    asm("mov.b64 {%0, %1}, %2;" : "=r"(lo), "=r"(hi) : "l"(v));
    return make_float2(__uint_as_float(lo), __uint_as_float(hi));
}
__device__ __forceinline__ void ffma2(ull& acc, ull a, ull b) {
    asm("fma.rn.f32x2 %0, %1, %2, %0;" : "+l"(acc) : "l"(a), "l"(b));
}

// Exact order-preserving 64-bit key: high32 = monotone float bits (FULL precision),
// low32 = ~m  -> unique keys; equal values order by LOWER index first (= reference).
__device__ __forceinline__ ull packkey(float v, int m) {
    unsigned u = __float_as_uint(v);
    u ^= ((unsigned)((int)u >> 31)) | 0x80000000u;
    return ((ull)u << 32) | (ull)(0xFFFFFFFFu - (unsigned)m);
}

// ---------------- scratch (static __device__ — no allocations) ----------------
__device__ float g_xx[PTS];
__device__ float g_xt3[PTS * 3];
__device__ int   g_idx[PTS * KNN];
__device__ float g_feat[2][BB * 64 * NN];              // [c][n] layout (for knn)
__device__ float g_featt[2][(size_t)PTS * 64];         // [n][c] layout (for gather)
__device__ float g_base[PTS * 64];
__device__ float g_hacc[(size_t)PTS * KNN * 64];
__device__ float g_hm[BB * 64 * NN];
__device__ float g_h2t[(size_t)PTS * 256];
__device__ float g_pmax[BB * 32 * 256];
__device__ float g_psum[BB * 32 * 256];
__device__ float g_gvec[BB * 512];

// ---------------- stage-1 norms + transpose ----------------
__global__ void xx3t_kernel(const float* __restrict__ x) {
    int t = blockIdx.x * blockDim.x + threadIdx.x;
    if (t >= PTS) return;
    int b = t / NN, n = t % NN;
    float v0 = x[(b * 3 + 0) * NN + n];
    float v1 = x[(b * 3 + 1) * NN + n];
    float v2 = x[(b * 3 + 2) * NN + n];
    g_xx[t] = v0 * v0 + v1 * v1 + v2 * v2;
    g_xt3[t * 3 + 0] = v0;
    g_xt3[t * 3 + 1] = v1;
    g_xt3[t * 3 + 2] = v2;
}

// ---------------- top-k: EXACT register-resident bubble-carry insert ---------
struct TopK {
    float v[KNN];
    int   id[KNN];
    float thr;
    __device__ __forceinline__ void init() {
#pragma unroll
        for (int i = 0; i < KNN; i++) { v[i] = -3e38f; id[i] = 0; }
        thr = -3e38f;
    }
    __device__ __forceinline__ void push(float val, int m) {
        if (val > thr) {
            float cv = val; int ci = m;
#pragma unroll
            for (int i = 0; i < KNN; i++) {
                bool sw = (cv > v[i]);
                float nv = sw ? cv : v[i];
                int   ni = sw ? ci : id[i];
                cv = sw ? v[i] : cv;
                ci = sw ? id[i] : ci;
                v[i] = nv; id[i] = ni;
            }
            thr = v[KNN - 1];
        }
    }
};

// ---------------- 4-way merge of sorted packed-key lists (exact) -------------
__device__ __forceinline__ void merge4_to(const ull* L0, const ull* L1,
                                          const ull* L2, const ull* L3, int* op) {
    int p0 = 0, p1 = 0, p2 = 0, p3 = 0;
#pragma unroll
    for (int k = 0; k < KNN; k++) {
        ull a = L0[p0], b = L1[p1], c = L2[p2], d = L3[p3];
        ull best = a; int src = 0;
        if (b > best) { best = b; src = 1; }
        if (c > best) { best = c; src = 2; }
        if (d > best) { best = d; src = 3; }
        op[k] = (int)(0xFFFFFFFFu - (unsigned)(best & 0xFFFFFFFFull));
        if (src == 0) p0++; else if (src == 1) p1++; else if (src == 2) p2++; else p3++;
    }
}

// ---------------- kNN, C=3 (stage 1): 32 queries x 4 groups, 128 thr ---------
__global__ __launch_bounds__(128) void knn3_kernel(const float* __restrict__ x) {
    __shared__ __align__(16) float sm[4][NN];  // 32KB tile; lists g1-3 overlay after
    __shared__ ull l0[32 * KNN];               // 5KB group-0 lists
    int b = blockIdx.y;
    int tid = threadIdx.x;
    int q = tid & 31, g = tid >> 5;            // group == warp id (uniform)
    int n = blockIdx.x * 32 + q;
    for (int i = tid; i < NN; i += 128) {
        sm[0][i] = x[(b * 3 + 0) * NN + i];
        sm[1][i] = x[(b * 3 + 1) * NN + i];
        sm[2][i] = x[(b * 3 + 2) * NN + i];
        sm[3][i] = g_xx[b * NN + i];
    }
    __syncthreads();
    float q0 = sm[0][n], q1 = sm[1][n], q2 = sm[2][n], xq = sm[3][n];
    TopK tk; tk.init();
    int mbase = g * 512;
    for (int m = mbase; m < mbase + 512; m++) {
        float d = q0 * sm[0][m] + q1 * sm[1][m] + q2 * sm[2][m];
        tk.push(2.f * d - xq - sm[3][m], m);
    }
    __syncthreads();                            // all reads of sm done
    ull* lg = (g == 0) ? &l0[q * KNN] : ((ull*)sm) + ((g - 1) * 32 + q) * KNN;
#pragma unroll
    for (int k = 0; k < KNN; k++) lg[k] = packkey(tk.v[k], tk.id[k]);
    __syncthreads();
    if (tid < 32) {
        merge4_to(&l0[tid * KNN],
                  ((ull*)sm) + (0 * 32 + tid) * KNN,
                  ((ull*)sm) + (1 * 32 + tid) * KNN,
                  ((ull*)sm) + (2 * 32 + tid) * KNN,
                  g_idx + (b * NN + blockIdx.x * 32 + tid) * KNN);
    }
}

// ---------------- kNN, C=64: 32 queries x 4 groups, 128 thr + f32x2 ----------
__global__ __launch_bounds__(128) void knn64_kernel(int sel) {
    const float* x = g_feat[sel];               // [b][64][NN]
    __shared__ __align__(16) float4 s4[4 * 512]; // 32KB; per-group 32-cand tile
    __shared__ float sxx[4][32];
    __shared__ ull l0[32 * KNN];                // 5KB group-0 lists
    int b = blockIdx.y;
    int tid = threadIdx.x;
    int q = tid & 31, g = tid >> 5;             // group == warp id (uniform)
    int n = blockIdx.x * 32 + q;
    float qf[64];
#pragma unroll
    for (int c = 0; c < 64; c++) qf[c] = x[(b * 64 + c) * NN + n];
    float xq = g_xx[b * NN + n];
    TopK tk; tk.init();
    int mbase = g * 512;
    float4* sg = s4 + g * 512;
    for (int m0 = 0; m0 < 512; m0 += 32) {
        __syncthreads();
        for (int i = q; i < 512; i += 32) {     // 512 float4 = 64 ch x 32 cands
            int c = i >> 3, j = i & 7;
            sg[i] = *(const float4*)&x[(b * 64 + c) * NN + mbase + m0 + j * 4];
        }
        sxx[g][q] = g_xx[b * NN + mbase + m0 + q];
        __syncthreads();
        for (int j8 = 0; j8 < 4; j8++) {        // 8 candidates per iteration
            ull d01 = 0, d23 = 0, d45 = 0, d67 = 0;
#pragma unroll
            for (int c = 0; c < 64; c++) {      // FULL unroll: qf stays in regs
                ull q2 = splat2(qf[c]);
                ulonglong2 va = *(const ulonglong2*)&sg[c * 8 + j8 * 2];
                ulonglong2 vb = *(const ulonglong2*)&sg[c * 8 + j8 * 2 + 1];
                ffma2(d01, q2, va.x); ffma2(d23, q2, va.y);
                ffma2(d45, q2, vb.x); ffma2(d67, q2, vb.y);
            }
            int m = mbase + m0 + j8 * 8;
            int jb = j8 * 8;
            float2 p;
            p = unpack2(d01);
            tk.push(2.f * p.x - xq - sxx[g][jb + 0], m + 0);
            tk.push(2.f * p.y - xq - sxx[g][jb + 1], m + 1);
            p = unpack2(d23);
            tk.push(2.f * p.x - xq - sxx[g][jb + 2], m + 2);
            tk.push(2.f * p.y - xq - sxx[g][jb + 3], m + 3);
            p = unpack2(d45);
            tk.push(2.f * p.x - xq - sxx[g][jb + 4], m + 4);
            tk.push(2.f * p.y - xq - sxx[g][jb + 5], m + 5);
            p = unpack2(d67);
            tk.push(2.f * p.x - xq - sxx[g][jb + 6], m + 6);
            tk.push(2.f * p.y - xq - sxx[g][jb + 7], m + 7);
        }
    }
    __syncthreads();                            // all reads of s4 done
    ull* lg = (g == 0) ? &l0[q * KNN] : ((ull*)s4) + ((g - 1) * 32 + q) * KNN;
#pragma unroll
    for (int k = 0; k < KNN; k++) lg[k] = packkey(tk.v[k], tk.id[k]);
    __syncthreads();
    if (tid < 32) {
        merge4_to(&l0[tid * KNN],
                  ((ull*)s4) + (0 * 32 + tid) * KNN,
                  ((ull*)s4) + (1 * 32 + tid) * KNN,
                  ((ull*)s4) + (2 * 32 + tid) * KNN,
                  g_idx + (b * NN + blockIdx.x * 32 + tid) * KNN);
    }
}

// ---------------- base = (Wc - Wd) @ ctr ----------------
template <int C>
__global__ __launch_bounds__(128) void base_kernel(const float* __restrict__ w, int selt) {
    __shared__ float wcd[64 * C];
    const float* xt = (C == 3) ? g_xt3 : g_featt[selt];
    int tid = threadIdx.x;
    for (int i = tid; i < 64 * C; i += 128) {
        int o = i / C, c = i - o * C;
        wcd[i] = w[o * 2 * C + C + c] - w[o * 2 * C + c];
    }
    __syncthreads();
    int p = blockIdx.x * 128 + tid;
    float xr[C];
#pragma unroll
    for (int c = 0; c < C; c++) xr[c] = xt[(size_t)p * C + c];
#pragma unroll 4
    for (int o = 0; o < 64; o++) {
        float a = 0.f;
#pragma unroll
        for (int c = 0; c < C; c++) a += wcd[o * C + c] * xr[c];
        g_base[p * 64 + o] = a;
    }
}

// ---------------- EdgeConv + fused w5-slice accumulate, f32x2 GEMMs ----------
template <int C, int ACCUM, int FINAL, int WRITEX>
__global__ __launch_bounds__(96) void edge_kernel(
    int selin,
    const float* __restrict__ w,    // [64][2C]
    const float* __restrict__ bnp,  // [4][64]
    const float* __restrict__ w5,   // [64][256]
    int w5off, int selout,
    const float* __restrict__ bnp5)
{
    __shared__ __align__(16) float sm[C * 64 + 4096 + 3 * 1280];
    __shared__ int sid[3][KNN];
    const float* xin_t = (C == 3) ? g_xt3 : g_featt[selin];
    float* xout  = g_feat[selout];
    float* xoutt = g_featt[selout];
    float* wd2 = sm;                 // [C][64]: (Wd[j][c], Wd[j+32][c])
    float* w52 = sm + C * 64;        // [64][64]: (w5[j][off+o], w5[j+32][off+o])
    int tid = threadIdx.x;
    float* wbuf = sm + C * 64 + 4096 + (tid >> 5) * 1280;

    for (int i = tid; i < C * 64; i += 96) {
        int c = i >> 6, t2 = i & 63, jj = t2 >> 1, hi = t2 & 1;
        wd2[i] = w[(jj + 32 * hi) * (2 * C) + c];
    }
    for (int i = tid; i < 4096; i += 96) {
        int o = i >> 6, t2 = i & 63, jj = t2 >> 1, hi = t2 & 1;
        w52[i] = w5[(jj + 32 * hi) * 256 + w5off + o];
    }
    __syncthreads();

    int lane = tid & 31, warp = tid >> 5;
    int* myid = sid[warp];
    float a0 = bnp[lane] * rsqrtf(bnp[192 + lane] + EPSBN);
    float c0 = bnp[64 + lane] - bnp[128 + lane] * a0;
    float a1 = bnp[32 + lane] * rsqrtf(bnp[224 + lane] + EPSBN);
    float c1 = bnp[96 + lane] - bnp[160 + lane] * a1;
    float a5l = 0.f, c5l = 0.f, a5h = 0.f, c5h = 0.f;
    if (FINAL) {
        a5l = bnp5[lane] * rsqrtf(bnp5[192 + lane] + EPSBN);
        c5l = bnp5[64 + lane] - bnp5[128 + lane] * a5l;
        a5h = bnp5[32 + lane] * rsqrtf(bnp5[224 + lane] + EPSBN);
        c5h = bnp5[96 + lane] - bnp5[160 + lane] * a5h;
    }

    for (int p = blockIdx.x * 3 + warp; p < PTS; p += gridDim.x * 3) {
        int b = p >> 11, n = p & (NN - 1);
        if (lane < KNN) myid[lane] = g_idx[p * KNN + lane];
        __syncwarp();
        if (C == 64) {
#pragma unroll
            for (int i = 0; i < 10; i++) {
                int idx = lane + i * 32;
                int k = idx >> 4, c4 = idx & 15;
                int nb = myid[k];
                float4 v = *(const float4*)&xin_t[((size_t)b * NN + nb) * 64 + c4 * 4];
                wbuf[(c4 * 4 + 0) * KNN + k] = v.x;
                wbuf[(c4 * 4 + 1) * KNN + k] = v.y;
                wbuf[(c4 * 4 + 2) * KNN + k] = v.z;
                wbuf[(c4 * 4 + 3) * KNN + k] = v.w;
            }
        } else {
            for (int t = lane; t < C * KNN; t += 32) {
                int k = t / C, c = t - k * C;
                wbuf[c * KNN + k] = xin_t[((size_t)b * NN + myid[k]) * C + c];
            }
        }
        __syncwarp();
        ull acc0p[10], acc1p[10];
        {
            ull b0 = splat2(g_base[p * 64 + lane]);
            ull b1 = splat2(g_base[p * 64 + 32 + lane]);
#pragma unroll
            for (int i = 0; i < 10; i++) { acc0p[i] = b0; acc1p[i] = b1; }
        }
#pragma unroll 8
        for (int c = 0; c < C; c++) {
            float2 wv = *(const float2*)&wd2[c * 64 + 2 * lane];
            ull wx = splat2(wv.x), wy = splat2(wv.y);
            const ulonglong2* nb2 = (const ulonglong2*)&wbuf[c * KNN];
#pragma unroll
            for (int qd = 0; qd < 5; qd++) {
                ulonglong2 v = nb2[qd];
                ffma2(acc0p[2 * qd], wx, v.x); ffma2(acc0p[2 * qd + 1], wx, v.y);
                ffma2(acc1p[2 * qd], wy, v.x); ffma2(acc1p[2 * qd + 1], wy, v.y);
            }
        }
        __syncwarp();
        float ym0 = -3e38f, ym1 = -3e38f;
#pragma unroll
        for (int i = 0; i < 10; i++) {
            float2 u0 = unpack2(acc0p[i]);
            float2 u1 = unpack2(acc1p[i]);
            float y00 = a0 * u0.x + c0; y00 = (y00 >= 0.f) ? y00 : 0.2f * y00;
            float y01 = a0 * u0.y + c0; y01 = (y01 >= 0.f) ? y01 : 0.2f * y01;
            float y10 = a1 * u1.x + c1; y10 = (y10 >= 0.f) ? y10 : 0.2f * y10;
            float y11 = a1 * u1.y + c1; y11 = (y11 >= 0.f) ? y11 : 0.2f * y11;
            ym0 = fmaxf(ym0, fmaxf(y00, y01));
            ym1 = fmaxf(ym1, fmaxf(y10, y11));
            *(ull*)&wbuf[lane * KNN + 2 * i]        = pack2(y00, y01);
            *(ull*)&wbuf[(lane + 32) * KNN + 2 * i] = pack2(y10, y11);
        }
        __syncwarp();
        ull h0p[10], h1p[10];
#pragma unroll
        for (int i = 0; i < 10; i++) { h0p[i] = 0ull; h1p[i] = 0ull; }
#pragma unroll 8
        for (int o = 0; o < 64; o++) {
            float2 wv = *(const float2*)&w52[o * 64 + 2 * lane];
            ull wx = splat2(wv.x), wy = splat2(wv.y);
            const ulonglong2* y2 = (const ulonglong2*)&wbuf[o * KNN];
#pragma unroll
            for (int qd = 0; qd < 5; qd++) {
                ulonglong2 v = y2[qd];
                ffma2(h0p[2 * qd], wx, v.x); ffma2(h0p[2 * qd + 1], wx, v.y);
                ffma2(h1p[2 * qd], wy, v.x); ffma2(h1p[2 * qd + 1], wy, v.y);
            }
        }
        float* hp = g_hacc + (size_t)p * KNN * 64;
        if (FINAL) {
            float m0 = -3e38f, m1 = -3e38f;
#pragma unroll
            for (int i = 0; i < 10; i++) {
                float2 h0 = unpack2(h0p[i]);
                float2 h1 = unpack2(h1p[i]);
                float v00 = a5l * (hp[(2 * i) * 64 + lane] + h0.x) + c5l;
                v00 = (v00 >= 0.f) ? v00 : 0.2f * v00;
                float v01 = a5l * (hp[(2 * i + 1) * 64 + lane] + h0.y) + c5l;
                v01 = (v01 >= 0.f) ? v01 : 0.2f * v01;
                float v10 = a5h * (hp[(2 * i) * 64 + 32 + lane] + h1.x) + c5h;
                v10 = (v10 >= 0.f) ? v10 : 0.2f * v10;
                float v11 = a5h * (hp[(2 * i + 1) * 64 + 32 + lane] + h1.y) + c5h;
                v11 = (v11 >= 0.f) ? v11 : 0.2f * v11;
                m0 = fmaxf(m0, fmaxf(v00, v01));
                m1 = fmaxf(m1, fmaxf(v10, v11));
            }
            g_hm[(b * 64 + lane) * NN + n]      = m0;
            g_hm[(b * 64 + 32 + lane) * NN + n] = m1;
        } else if (ACCUM) {
#pragma unroll
            for (int i = 0; i < 10; i++) {
                float2 h0 = unpack2(h0p[i]);
                float2 h1 = unpack2(h1p[i]);
                hp[(2 * i) * 64 + lane]          += h0.x;
                hp[(2 * i + 1) * 64 + lane]      += h0.y;
                hp[(2 * i) * 64 + 32 + lane]     += h1.x;
                hp[(2 * i + 1) * 64 + 32 + lane] += h1.y;
            }
        } else {
#pragma unroll
            for (int i = 0; i < 10; i++) {
                float2 h0 = unpack2(h0p[i]);
                float2 h1 = unpack2(h1p[i]);
                hp[(2 * i) * 64 + lane]          = h0.x;
                hp[(2 * i + 1) * 64 + lane]      = h0.y;
                hp[(2 * i) * 64 + 32 + lane]     = h1.x;
                hp[(2 * i + 1) * 64 + 32 + lane] = h1.y;
            }
        }
        if (WRITEX) {
            xout[(b * 64 + lane) * NN + n]      = ym0;
            xout[(b * 64 + 32 + lane) * NN + n] = ym1;
            xoutt[((size_t)b * NN + n) * 64 + lane]      = ym0;
            xoutt[((size_t)b * NN + n) * 64 + 32 + lane] = ym1;
            float xxv = ym0 * ym0 + ym1 * ym1;
#pragma unroll
            for (int off = 16; off > 0; off >>= 1)
                xxv += __shfl_xor_sync(0xffffffffu, xxv, off);
            if (lane == 0) g_xx[p] = xxv;
        }
        __syncwarp();
    }
}

// ---------------- conv6 (64 -> 256) + bn6 + lrelu ----------------
__global__ __launch_bounds__(256) void conv6_kernel(const float* __restrict__ w6,
                                                    const float* __restrict__ bnp) {
    __shared__ float sh[64 * 128];
    int b = blockIdx.y, n0 = blockIdx.x * 128;
    for (int i = threadIdx.x; i < 64 * 128; i += 256) {
        int c = i >> 7, j = i & 127;
        sh[i] = g_hm[(b * 64 + c) * NN + n0 + j];
    }
    int o2 = threadIdx.x;
    float wr[64];
#pragma unroll
    for (int o = 0; o < 64; o++) wr[o] = w6[o2 * 64 + o];
    float a = bnp[o2] * rsqrtf(bnp[768 + o2] + EPSBN);
    float cb = bnp[256 + o2] - bnp[512 + o2] * a;
    __syncthreads();
    for (int jj = 0; jj < 64; jj++) {
        float s0 = 0.f, s1 = 0.f;
#pragma unroll
        for (int o = 0; o < 64; o++) {
            float2 v = *(const float2*)&sh[o * 128 + jj * 2];
            s0 += wr[o] * v.x;
            s1 += wr[o] * v.y;
        }
        float v0 = a * s0 + cb; v0 = (v0 >= 0.f) ? v0 : 0.2f * v0;
        float v1 = a * s1 + cb; v1 = (v1 >= 0.f) ? v1 : 0.2f * v1;
        g_h2t[((size_t)b * NN + n0 + jj * 2) * 256 + o2] = v0;
        g_h2t[((size_t)b * NN + n0 + jj * 2 + 1) * 256 + o2] = v1;
    }
}

// ---------------- global max + mean over N (2-level) ----------------
__global__ void reduce1_kernel() {
    int b = blockIdx.y, s = blockIdx.x, o = threadIdx.x;
    float m = -3e38f, sum = 0.f;
#pragma unroll 8
    for (int j = 0; j < 64; j++) {
        float v = g_h2t[((size_t)b * NN + s * 64 + j) * 256 + o];
        m = fmaxf(m, v);
        sum += v;
    }
    g_pmax[(b * 32 + s) * 256 + o] = m;
    g_psum[(b * 32 + s) * 256 + o] = sum;
}
__global__ void reduce2_kernel() {
    int b = blockIdx.x, o = threadIdx.x;
    float m = -3e38f, s = 0.f;
#pragma unroll
    for (int j = 0; j < 32; j++) {
        m = fmaxf(m, g_pmax[(b * 32 + j) * 256 + o]);
        s += g_psum[(b * 32 + j) * 256 + o];
    }
    g_gvec[b * 512 + o] = m;
    g_gvec[b * 512 + 256 + o] = s * (1.0f / NN);
}

// ---------------- FC head ----------------
__global__ __launch_bounds__(256) void fc_kernel(
    const float* __restrict__ lw1, const float* __restrict__ lb1, const float* __restrict__ lbn1,
    const float* __restrict__ lw2, const float* __restrict__ lb2, const float* __restrict__ lbn2,
    const float* __restrict__ lw3, const float* __restrict__ lb3, float* __restrict__ out) {
    __shared__ float sg[512];
    __shared__ float sz[256];
    __shared__ float sz2[64];
    int b = blockIdx.x, t = threadIdx.x;
    sg[t] = g_gvec[b * 512 + t];
    sg[t + 256] = g_gvec[b * 512 + 256 + t];
    __syncthreads();
    {
        float acc = lb1[t];
#pragma unroll 8
        for (int i = 0; i < 512; i++) acc += lw1[t * 512 + i] * sg[i];
        float a = lbn1[t] * rsqrtf(lbn1[768 + t] + EPSBN);
        float cb = lbn1[256 + t] - lbn1[512 + t] * a;
        float v = a * acc + cb;
        sz[t] = (v >= 0.f) ? v : 0.01f * v;
    }
    __syncthreads();
    if (t < 64) {
        float acc = lb2[t];
#pragma unroll 8
        for (int i = 0; i < 256; i++) acc += lw2[t * 256 + i] * sz[i];
        float a = lbn2[t] * rsqrtf(lbn2[192 + t] + EPSBN);
        float cb = lbn2[64 + t] - lbn2[128 + t] * a;
        float v = a * acc + cb;
        sz2[t] = (v >= 0.f) ? v : 0.01f * v;
    }
    __syncthreads();
    if (t < CLSN) {
        float acc = lb3[t];
#pragma unroll
        for (int i = 0; i < 64; i++) acc += lw3[t * 64 + i] * sz2[i];
        out[b * CLSN + t] = acc;
    }
}

// ---------------- launch ----------------
extern "C" void kernel_launch(void* const* d_in, const int* in_sizes, int n_in,
                              void* d_out, int out_size) {
    const float* x    = (const float*)d_in[0];
    const float* w1   = (const float*)d_in[1];
    const float* bn1  = (const float*)d_in[2];
    const float* w2   = (const float*)d_in[3];
    const float* bn2  = (const float*)d_in[4];
    const float* w3   = (const float*)d_in[5];
    const float* bn3  = (const float*)d_in[6];
    const float* w4   = (const float*)d_in[7];
    const float* bn4  = (const float*)d_in[8];
    const float* w5   = (const float*)d_in[9];
    const float* bn5  = (const float*)d_in[10];
    const float* w6   = (const float*)d_in[11];
    const float* bn6  = (const float*)d_in[12];
    const float* lw1  = (const float*)d_in[13];
    const float* lb1  = (const float*)d_in[14];
    const float* lbn1 = (const float*)d_in[15];
    const float* lw2  = (const float*)d_in[16];
    const float* lb2  = (const float*)d_in[17];
    const float* lbn2 = (const float*)d_in[18];
    const float* lw3  = (const float*)d_in[19];
    const float* lb3  = (const float*)d_in[20];
    float* out = (float*)d_out;
    (void)in_sizes; (void)n_in; (void)out_size;

    dim3 knn_grid(NN / 32, BB);   // 64 x 8 = 512 blocks of 128 threads
    const int EG = 592;

    // stage 1 (input C=3)
    xx3t_kernel<<<(PTS + 255) / 256, 256>>>(x);
    knn3_kernel<<<knn_grid, 128>>>(x);
    base_kernel<3><<<PTS / 128, 128>>>(w1, 0);
    edge_kernel<3, 0, 0, 1><<<EG, 96>>>(0, w1, bn1, w5, 0, 0, nullptr);
    // stage 2
    knn64_kernel<<<knn_grid, 128>>>(0);
    base_kernel<64><<<PTS / 128, 128>>>(w2, 0);
    edge_kernel<64, 1, 0, 1><<<EG, 96>>>(0, w2, bn2, w5, 64, 1, nullptr);
    // stage 3
    knn64_kernel<<<knn_grid, 128>>>(1);
    base_kernel<64><<<PTS / 128, 128>>>(w3, 1);
    edge_kernel<64, 1, 0, 1><<<EG, 96>>>(1, w3, bn3, w5, 128, 0, nullptr);
    // stage 4 (fused bn5+lrelu+max_k)
    knn64_kernel<<<knn_grid, 128>>>(0);
    base_kernel<64><<<PTS / 128, 128>>>(w4, 0);
    edge_kernel<64, 1, 1, 0><<<EG, 96>>>(0, w4, bn4, w5, 192, 1, bn5);
    // tail
    conv6_kernel<<<dim3(NN / 128, BB), 256>>>(w6, bn6);
    reduce1_kernel<<<dim3(32, BB), 256>>>();
    reduce2_kernel<<<BB, 256>>>();
    fc_kernel<<<BB, 256>>>(lw1, lb1, lbn1, lw2, lb2, lbn2, lw3, lb3, out);
}

// round 16
// speedup vs baseline: 1.1707x; 1.0286x over previous
#include <cuda_runtime.h>
#include <math.h>

#define BB   8
#define NN   2048
#define KNN  20
#define CLSN 40
#define EPSBN 1e-5f
#define PTS  (BB * NN)

typedef unsigned long long ull;

// ---------------- f32x2 packed-math helpers (sm_100a) ----------------
__device__ __forceinline__ ull splat2(float x) {
    unsigned u = __float_as_uint(x);
    ull r;
    asm("mov.b64 %0, {%1, %1};" : "=l"(r) : "r"(u));
    return r;
}
__device__ __forceinline__ ull pack2(float x, float y) {
    ull r;
    asm("mov.b64 %0, {%1, %2};" : "=l"(r) : "r"(__float_as_uint(x)), "r"(__float_as_uint(y)));
    return r;
}
__device__ __forceinline__ float2 unpack2(ull v) {
    unsigned lo, hi;
    asm("mov.b64 {%0, %1}, %2;" : "=r"(lo), "=r"(hi) : "l"(v));
    return make_float2(__uint_as_float(lo), __uint_as_float(hi));
}
__device__ __forceinline__ void ffma2(ull& acc, ull a, ull b) {
    asm("fma.rn.f32x2 %0, %1, %2, %0;" : "+l"(acc) : "l"(a), "l"(b));
}

// Exact order-preserving 64-bit key: high32 = monotone float bits (FULL precision),
// low32 = ~m  -> unique keys; equal values order by LOWER index first (= reference).
__device__ __forceinline__ ull packkey(float v, int m) {
    unsigned u = __float_as_uint(v);
    u ^= ((unsigned)((int)u >> 31)) | 0x80000000u;
    return ((ull)u << 32) | (ull)(0xFFFFFFFFu - (unsigned)m);
}

// ---------------- scratch (static __device__ — no allocations) ----------------
__device__ float g_xx[PTS];
__device__ float g_xt3[PTS * 3];
__device__ int   g_idx[PTS * KNN];
__device__ float g_feat[2][BB * 64 * NN];              // [c][n] layout (for knn)
__device__ float g_featt[2][(size_t)PTS * 64];         // [n][c] layout (for gather)
__device__ float g_base[PTS * 64];
__device__ float g_hacc[(size_t)PTS * KNN * 64];
__device__ float g_hm[BB * 64 * NN];
__device__ float g_pmax[BB * 16 * 256];
__device__ float g_psum[BB * 16 * 256];
__device__ float g_gvec[BB * 512];

// ---------------- stage-1 norms + transpose ----------------
__global__ void xx3t_kernel(const float* __restrict__ x) {
    int t = blockIdx.x * blockDim.x + threadIdx.x;
    if (t >= PTS) return;
    int b = t / NN, n = t % NN;
    float v0 = x[(b * 3 + 0) * NN + n];
    float v1 = x[(b * 3 + 1) * NN + n];
    float v2 = x[(b * 3 + 2) * NN + n];
    g_xx[t] = v0 * v0 + v1 * v1 + v2 * v2;
    g_xt3[t * 3 + 0] = v0;
    g_xt3[t * 3 + 1] = v1;
    g_xt3[t * 3 + 2] = v2;
}

// ---------------- top-k: EXACT register-resident bubble-carry insert ---------
struct TopK {
    float v[KNN];
    int   id[KNN];
    float thr;
    __device__ __forceinline__ void init() {
#pragma unroll
        for (int i = 0; i < KNN; i++) { v[i] = -3e38f; id[i] = 0; }
        thr = -3e38f;
    }
    __device__ __forceinline__ void push(float val, int m) {
        if (val > thr) {
            float cv = val; int ci = m;
#pragma unroll
            for (int i = 0; i < KNN; i++) {
                bool sw = (cv > v[i]);
                float nv = sw ? cv : v[i];
                int   ni = sw ? ci : id[i];
                cv = sw ? v[i] : cv;
                ci = sw ? id[i] : ci;
                v[i] = nv; id[i] = ni;
            }
            thr = v[KNN - 1];
        }
    }
};

// ---------------- 4-way merge of sorted packed-key lists (exact) -------------
__device__ __forceinline__ void merge4_to(const ull* L0, const ull* L1,
                                          const ull* L2, const ull* L3, int* op) {
    int p0 = 0, p1 = 0, p2 = 0, p3 = 0;
#pragma unroll
    for (int k = 0; k < KNN; k++) {
        ull a = L0[p0], b = L1[p1], c = L2[p2], d = L3[p3];
        ull best = a; int src = 0;
        if (b > best) { best = b; src = 1; }
        if (c > best) { best = c; src = 2; }
        if (d > best) { best = d; src = 3; }
        op[k] = (int)(0xFFFFFFFFu - (unsigned)(best & 0xFFFFFFFFull));
        if (src == 0) p0++; else if (src == 1) p1++; else if (src == 2) p2++; else p3++;
    }
}

// ---------------- kNN, C=3 (stage 1): 32 queries x 4 groups, 128 thr ---------
__global__ __launch_bounds__(128) void knn3_kernel(const float* __restrict__ x) {
    __shared__ __align__(16) float sm[4][NN];  // 32KB tile; lists g1-3 overlay after
    __shared__ ull l0[32 * KNN];               // 5KB group-0 lists
    int b = blockIdx.y;
    int tid = threadIdx.x;
    int q = tid & 31, g = tid >> 5;            // group == warp id (uniform)
    int n = blockIdx.x * 32 + q;
    for (int i = tid; i < NN; i += 128) {
        sm[0][i] = x[(b * 3 + 0) * NN + i];
        sm[1][i] = x[(b * 3 + 1) * NN + i];
        sm[2][i] = x[(b * 3 + 2) * NN + i];
        sm[3][i] = g_xx[b * NN + i];
    }
    __syncthreads();
    float q0 = sm[0][n], q1 = sm[1][n], q2 = sm[2][n], xq = sm[3][n];
    TopK tk; tk.init();
    int mbase = g * 512;
    for (int m = mbase; m < mbase + 512; m++) {
        float d = q0 * sm[0][m] + q1 * sm[1][m] + q2 * sm[2][m];
        tk.push(2.f * d - xq - sm[3][m], m);
    }
    __syncthreads();                            // all reads of sm done
    ull* lg = (g == 0) ? &l0[q * KNN] : ((ull*)sm) + ((g - 1) * 32 + q) * KNN;
#pragma unroll
    for (int k = 0; k < KNN; k++) lg[k] = packkey(tk.v[k], tk.id[k]);
    __syncthreads();
    if (tid < 32) {
        merge4_to(&l0[tid * KNN],
                  ((ull*)sm) + (0 * 32 + tid) * KNN,
                  ((ull*)sm) + (1 * 32 + tid) * KNN,
                  ((ull*)sm) + (2 * 32 + tid) * KNN,
                  g_idx + (b * NN + blockIdx.x * 32 + tid) * KNN);
    }
}

// ---------------- kNN, C=64: 32 queries x 4 groups, 128 thr + f32x2 ----------
__global__ __launch_bounds__(128) void knn64_kernel(int sel) {
    const float* x = g_feat[sel];               // [b][64][NN]
    __shared__ __align__(16) float4 s4[4 * 512]; // 32KB; per-group 32-cand tile
    __shared__ float sxx[4][32];
    __shared__ ull l0[32 * KNN];                // 5KB group-0 lists
    int b = blockIdx.y;
    int tid = threadIdx.x;
    int q = tid & 31, g = tid >> 5;             // group == warp id (uniform)
    int n = blockIdx.x * 32 + q;
    float qf[64];
#pragma unroll
    for (int c = 0; c < 64; c++) qf[c] = x[(b * 64 + c) * NN + n];
    float xq = g_xx[b * NN + n];
    TopK tk; tk.init();
    int mbase = g * 512;
    float4* sg = s4 + g * 512;
    for (int m0 = 0; m0 < 512; m0 += 32) {
        __syncthreads();
        for (int i = q; i < 512; i += 32) {     // 512 float4 = 64 ch x 32 cands
            int c = i >> 3, j = i & 7;
            sg[i] = *(const float4*)&x[(b * 64 + c) * NN + mbase + m0 + j * 4];
        }
        sxx[g][q] = g_xx[b * NN + mbase + m0 + q];
        __syncthreads();
        for (int j8 = 0; j8 < 4; j8++) {        // 8 candidates per iteration
            ull d01 = 0, d23 = 0, d45 = 0, d67 = 0;
#pragma unroll
            for (int c = 0; c < 64; c++) {      // FULL unroll: qf stays in regs
                ull q2 = splat2(qf[c]);
                ulonglong2 va = *(const ulonglong2*)&sg[c * 8 + j8 * 2];
                ulonglong2 vb = *(const ulonglong2*)&sg[c * 8 + j8 * 2 + 1];
                ffma2(d01, q2, va.x); ffma2(d23, q2, va.y);
                ffma2(d45, q2, vb.x); ffma2(d67, q2, vb.y);
            }
            int m = mbase + m0 + j8 * 8;
            int jb = j8 * 8;
            float2 p;
            p = unpack2(d01);
            tk.push(2.f * p.x - xq - sxx[g][jb + 0], m + 0);
            tk.push(2.f * p.y - xq - sxx[g][jb + 1], m + 1);
            p = unpack2(d23);
            tk.push(2.f * p.x - xq - sxx[g][jb + 2], m + 2);
            tk.push(2.f * p.y - xq - sxx[g][jb + 3], m + 3);
            p = unpack2(d45);
            tk.push(2.f * p.x - xq - sxx[g][jb + 4], m + 4);
            tk.push(2.f * p.y - xq - sxx[g][jb + 5], m + 5);
            p = unpack2(d67);
            tk.push(2.f * p.x - xq - sxx[g][jb + 6], m + 6);
            tk.push(2.f * p.y - xq - sxx[g][jb + 7], m + 7);
        }
    }
    __syncthreads();                            // all reads of s4 done
    ull* lg = (g == 0) ? &l0[q * KNN] : ((ull*)s4) + ((g - 1) * 32 + q) * KNN;
#pragma unroll
    for (int k = 0; k < KNN; k++) lg[k] = packkey(tk.v[k], tk.id[k]);
    __syncthreads();
    if (tid < 32) {
        merge4_to(&l0[tid * KNN],
                  ((ull*)s4) + (0 * 32 + tid) * KNN,
                  ((ull*)s4) + (1 * 32 + tid) * KNN,
                  ((ull*)s4) + (2 * 32 + tid) * KNN,
                  g_idx + (b * NN + blockIdx.x * 32 + tid) * KNN);
    }
}

// ---------------- base = (Wc - Wd) @ ctr  (C=64 stages only) -----------------
template <int C>
__global__ __launch_bounds__(128) void base_kernel(const float* __restrict__ w, int selt) {
    __shared__ float wcd[64 * C];
    const float* xt = (C == 3) ? g_xt3 : g_featt[selt];
    int tid = threadIdx.x;
    for (int i = tid; i < 64 * C; i += 128) {
        int o = i / C, c = i - o * C;
        wcd[i] = w[o * 2 * C + C + c] - w[o * 2 * C + c];
    }
    __syncthreads();
    int p = blockIdx.x * 128 + tid;
    float xr[C];
#pragma unroll
    for (int c = 0; c < C; c++) xr[c] = xt[(size_t)p * C + c];
#pragma unroll 4
    for (int o = 0; o < 64; o++) {
        float a = 0.f;
#pragma unroll
        for (int c = 0; c < C; c++) a += wcd[o * C + c] * xr[c];
        g_base[p * 64 + o] = a;
    }
}

// ---------------- EdgeConv + fused w5-slice accumulate, f32x2 GEMMs ----------
// B3: inline base computation for C=3 (removes the separate base3 launch).
template <int C, int ACCUM, int FINAL, int WRITEX, int B3>
__global__ __launch_bounds__(96) void edge_kernel(
    int selin,
    const float* __restrict__ w,    // [64][2C]
    const float* __restrict__ bnp,  // [4][64]
    const float* __restrict__ w5,   // [64][256]
    int w5off, int selout,
    const float* __restrict__ bnp5)
{
    __shared__ __align__(16) float sm[C * 64 + 4096 + 3 * 1280];
    __shared__ int sid[3][KNN];
    __shared__ float wcd3[3 * 64];   // (Wc-Wd) interleaved, used when B3
    const float* xin_t = (C == 3) ? g_xt3 : g_featt[selin];
    float* xout  = g_feat[selout];
    float* xoutt = g_featt[selout];
    float* wd2 = sm;                 // [C][64]: (Wd[j][c], Wd[j+32][c])
    float* w52 = sm + C * 64;        // [64][64]: (w5[j][off+o], w5[j+32][off+o])
    int tid = threadIdx.x;
    float* wbuf = sm + C * 64 + 4096 + (tid >> 5) * 1280;

    for (int i = tid; i < C * 64; i += 96) {
        int c = i >> 6, t2 = i & 63, jj = t2 >> 1, hi = t2 & 1;
        wd2[i] = w[(jj + 32 * hi) * (2 * C) + c];
    }
    if (B3) {
        for (int i = tid; i < 3 * 64; i += 96) {
            int c = i >> 6, t2 = i & 63, jj = t2 >> 1, hi = t2 & 1;
            int o = jj + 32 * hi;
            wcd3[i] = w[o * 6 + 3 + c] - w[o * 6 + c];
        }
    }
    for (int i = tid; i < 4096; i += 96) {
        int o = i >> 6, t2 = i & 63, jj = t2 >> 1, hi = t2 & 1;
        w52[i] = w5[(jj + 32 * hi) * 256 + w5off + o];
    }
    __syncthreads();

    int lane = tid & 31, warp = tid >> 5;
    int* myid = sid[warp];
    float a0 = bnp[lane] * rsqrtf(bnp[192 + lane] + EPSBN);
    float c0 = bnp[64 + lane] - bnp[128 + lane] * a0;
    float a1 = bnp[32 + lane] * rsqrtf(bnp[224 + lane] + EPSBN);
    float c1 = bnp[96 + lane] - bnp[160 + lane] * a1;
    float a5l = 0.f, c5l = 0.f, a5h = 0.f, c5h = 0.f;
    if (FINAL) {
        a5l = bnp5[lane] * rsqrtf(bnp5[192 + lane] + EPSBN);
        c5l = bnp5[64 + lane] - bnp5[128 + lane] * a5l;
        a5h = bnp5[32 + lane] * rsqrtf(bnp5[224 + lane] + EPSBN);
        c5h = bnp5[96 + lane] - bnp5[160 + lane] * a5h;
    }

    for (int p = blockIdx.x * 3 + warp; p < PTS; p += gridDim.x * 3) {
        int b = p >> 11, n = p & (NN - 1);
        if (lane < KNN) myid[lane] = g_idx[p * KNN + lane];
        __syncwarp();
        if (C == 64) {
#pragma unroll
            for (int i = 0; i < 10; i++) {
                int idx = lane + i * 32;
                int k = idx >> 4, c4 = idx & 15;
                int nb = myid[k];
                float4 v = *(const float4*)&xin_t[((size_t)b * NN + nb) * 64 + c4 * 4];
                wbuf[(c4 * 4 + 0) * KNN + k] = v.x;
                wbuf[(c4 * 4 + 1) * KNN + k] = v.y;
                wbuf[(c4 * 4 + 2) * KNN + k] = v.z;
                wbuf[(c4 * 4 + 3) * KNN + k] = v.w;
            }
        } else {
            for (int t = lane; t < C * KNN; t += 32) {
                int k = t / C, c = t - k * C;
                wbuf[c * KNN + k] = xin_t[((size_t)b * NN + myid[k]) * C + c];
            }
        }
        __syncwarp();
        float base0, base1;
        if (B3 && C == 3) {
            float x0 = g_xt3[p * 3 + 0];
            float x1 = g_xt3[p * 3 + 1];
            float x2 = g_xt3[p * 3 + 2];
            float t0 = 0.f, t1 = 0.f;
            t0 += wcd3[0 * 64 + 2 * lane] * x0;
            t0 += wcd3[1 * 64 + 2 * lane] * x1;
            t0 += wcd3[2 * 64 + 2 * lane] * x2;
            t1 += wcd3[0 * 64 + 2 * lane + 1] * x0;
            t1 += wcd3[1 * 64 + 2 * lane + 1] * x1;
            t1 += wcd3[2 * 64 + 2 * lane + 1] * x2;
            base0 = t0; base1 = t1;
        } else {
            base0 = g_base[p * 64 + lane];
            base1 = g_base[p * 64 + 32 + lane];
        }
        ull acc0p[10], acc1p[10];
        {
            ull b0 = splat2(base0);
            ull b1 = splat2(base1);
#pragma unroll
            for (int i = 0; i < 10; i++) { acc0p[i] = b0; acc1p[i] = b1; }
        }
#pragma unroll 8
        for (int c = 0; c < C; c++) {
            float2 wv = *(const float2*)&wd2[c * 64 + 2 * lane];
            ull wx = splat2(wv.x), wy = splat2(wv.y);
            const ulonglong2* nb2 = (const ulonglong2*)&wbuf[c * KNN];
#pragma unroll
            for (int qd = 0; qd < 5; qd++) {
                ulonglong2 v = nb2[qd];
                ffma2(acc0p[2 * qd], wx, v.x); ffma2(acc0p[2 * qd + 1], wx, v.y);
                ffma2(acc1p[2 * qd], wy, v.x); ffma2(acc1p[2 * qd + 1], wy, v.y);
            }
        }
        __syncwarp();
        float ym0 = -3e38f, ym1 = -3e38f;
#pragma unroll
        for (int i = 0; i < 10; i++) {
            float2 u0 = unpack2(acc0p[i]);
            float2 u1 = unpack2(acc1p[i]);
            float y00 = a0 * u0.x + c0; y00 = (y00 >= 0.f) ? y00 : 0.2f * y00;
            float y01 = a0 * u0.y + c0; y01 = (y01 >= 0.f) ? y01 : 0.2f * y01;
            float y10 = a1 * u1.x + c1; y10 = (y10 >= 0.f) ? y10 : 0.2f * y10;
            float y11 = a1 * u1.y + c1; y11 = (y11 >= 0.f) ? y11 : 0.2f * y11;
            ym0 = fmaxf(ym0, fmaxf(y00, y01));
            ym1 = fmaxf(ym1, fmaxf(y10, y11));
            *(ull*)&wbuf[lane * KNN + 2 * i]        = pack2(y00, y01);
            *(ull*)&wbuf[(lane + 32) * KNN + 2 * i] = pack2(y10, y11);
        }
        __syncwarp();
        ull h0p[10], h1p[10];
#pragma unroll
        for (int i = 0; i < 10; i++) { h0p[i] = 0ull; h1p[i] = 0ull; }
#pragma unroll 8
        for (int o = 0; o < 64; o++) {
            float2 wv = *(const float2*)&w52[o * 64 + 2 * lane];
            ull wx = splat2(wv.x), wy = splat2(wv.y);
            const ulonglong2* y2 = (const ulonglong2*)&wbuf[o * KNN];
#pragma unroll
            for (int qd = 0; qd < 5; qd++) {
                ulonglong2 v = y2[qd];
                ffma2(h0p[2 * qd], wx, v.x); ffma2(h0p[2 * qd + 1], wx, v.y);
                ffma2(h1p[2 * qd], wy, v.x); ffma2(h1p[2 * qd + 1], wy, v.y);
            }
        }
        float* hp = g_hacc + (size_t)p * KNN * 64;
        if (FINAL) {
            float m0 = -3e38f, m1 = -3e38f;
#pragma unroll
            for (int i = 0; i < 10; i++) {
                float2 h0 = unpack2(h0p[i]);
                float2 h1 = unpack2(h1p[i]);
                float v00 = a5l * (hp[(2 * i) * 64 + lane] + h0.x) + c5l;
                v00 = (v00 >= 0.f) ? v00 : 0.2f * v00;
                float v01 = a5l * (hp[(2 * i + 1) * 64 + lane] + h0.y) + c5l;
                v01 = (v01 >= 0.f) ? v01 : 0.2f * v01;
                float v10 = a5h * (hp[(2 * i) * 64 + 32 + lane] + h1.x) + c5h;
                v10 = (v10 >= 0.f) ? v10 : 0.2f * v10;
                float v11 = a5h * (hp[(2 * i + 1) * 64 + 32 + lane] + h1.y) + c5h;
                v11 = (v11 >= 0.f) ? v11 : 0.2f * v11;
                m0 = fmaxf(m0, fmaxf(v00, v01));
                m1 = fmaxf(m1, fmaxf(v10, v11));
            }
            g_hm[(b * 64 + lane) * NN + n]      = m0;
            g_hm[(b * 64 + 32 + lane) * NN + n] = m1;
        } else if (ACCUM) {
#pragma unroll
            for (int i = 0; i < 10; i++) {
                float2 h0 = unpack2(h0p[i]);
                float2 h1 = unpack2(h1p[i]);
                hp[(2 * i) * 64 + lane]          += h0.x;
                hp[(2 * i + 1) * 64 + lane]      += h0.y;
                hp[(2 * i) * 64 + 32 + lane]     += h1.x;
                hp[(2 * i + 1) * 64 + 32 + lane] += h1.y;
            }
        } else {
#pragma unroll
            for (int i = 0; i < 10; i++) {
                float2 h0 = unpack2(h0p[i]);
                float2 h1 = unpack2(h1p[i]);
                hp[(2 * i) * 64 + lane]          = h0.x;
                hp[(2 * i + 1) * 64 + lane]      = h0.y;
                hp[(2 * i) * 64 + 32 + lane]     = h1.x;
                hp[(2 * i + 1) * 64 + 32 + lane] = h1.y;
            }
        }
        if (WRITEX) {
            xout[(b * 64 + lane) * NN + n]      = ym0;
            xout[(b * 64 + 32 + lane) * NN + n] = ym1;
            xoutt[((size_t)b * NN + n) * 64 + lane]      = ym0;
            xoutt[((size_t)b * NN + n) * 64 + 32 + lane] = ym1;
            float xxv = ym0 * ym0 + ym1 * ym1;
#pragma unroll
            for (int off = 16; off > 0; off >>= 1)
                xxv += __shfl_xor_sync(0xffffffffu, xxv, off);
            if (lane == 0) g_xx[p] = xxv;
        }
        __syncwarp();
    }
}

// ---------------- conv6 (64 -> 256) + bn6 + lrelu + fused tile reduce --------
__global__ __launch_bounds__(256) void conv6_kernel(const float* __restrict__ w6,
                                                    const float* __restrict__ bnp) {
    __shared__ float sh[64 * 128];
    int b = blockIdx.y, tile = blockIdx.x, n0 = tile * 128;
    for (int i = threadIdx.x; i < 64 * 128; i += 256) {
        int c = i >> 7, j = i & 127;
        sh[i] = g_hm[(b * 64 + c) * NN + n0 + j];
    }
    int o2 = threadIdx.x;
    float wr[64];
#pragma unroll
    for (int o = 0; o < 64; o++) wr[o] = w6[o2 * 64 + o];
    float a = bnp[o2] * rsqrtf(bnp[768 + o2] + EPSBN);
    float cb = bnp[256 + o2] - bnp[512 + o2] * a;
    __syncthreads();
    float m = -3e38f, sum = 0.f;
    for (int jj = 0; jj < 64; jj++) {
        float s0 = 0.f, s1 = 0.f;
#pragma unroll
        for (int o = 0; o < 64; o++) {
            float2 v = *(const float2*)&sh[o * 128 + jj * 2];
            s0 += wr[o] * v.x;
            s1 += wr[o] * v.y;
        }
        float v0 = a * s0 + cb; v0 = (v0 >= 0.f) ? v0 : 0.2f * v0;
        float v1 = a * s1 + cb; v1 = (v1 >= 0.f) ? v1 : 0.2f * v1;
        m = fmaxf(m, fmaxf(v0, v1));
        sum += v0;
        sum += v1;
    }
    g_pmax[(b * 16 + tile) * 256 + o2] = m;
    g_psum[(b * 16 + tile) * 256 + o2] = sum;
}

// ---------------- final global max + mean over tiles ----------------
__global__ void reduce2_kernel() {
    int b = blockIdx.x, o = threadIdx.x;
    float m = -3e38f, s = 0.f;
#pragma unroll
    for (int j = 0; j < 16; j++) {
        m = fmaxf(m, g_pmax[(b * 16 + j) * 256 + o]);
        s += g_psum[(b * 16 + j) * 256 + o];
    }
    g_gvec[b * 512 + o] = m;
    g_gvec[b * 512 + 256 + o] = s * (1.0f / NN);
}

// ---------------- FC head ----------------
__global__ __launch_bounds__(256) void fc_kernel(
    const float* __restrict__ lw1, const float* __restrict__ lb1, const float* __restrict__ lbn1,
    const float* __restrict__ lw2, const float* __restrict__ lb2, const float* __restrict__ lbn2,
    const float* __restrict__ lw3, const float* __restrict__ lb3, float* __restrict__ out) {
    __shared__ float sg[512];
    __shared__ float sz[256];
    __shared__ float sz2[64];
    int b = blockIdx.x, t = threadIdx.x;
    sg[t] = g_gvec[b * 512 + t];
    sg[t + 256] = g_gvec[b * 512 + 256 + t];
    __syncthreads();
    {
        float acc = lb1[t];
#pragma unroll 8
        for (int i = 0; i < 512; i++) acc += lw1[t * 512 + i] * sg[i];
        float a = lbn1[t] * rsqrtf(lbn1[768 + t] + EPSBN);
        float cb = lbn1[256 + t] - lbn1[512 + t] * a;
        float v = a * acc + cb;
        sz[t] = (v >= 0.f) ? v : 0.01f * v;
    }
    __syncthreads();
    if (t < 64) {
        float acc = lb2[t];
#pragma unroll 8
        for (int i = 0; i < 256; i++) acc += lw2[t * 256 + i] * sz[i];
        float a = lbn2[t] * rsqrtf(lbn2[192 + t] + EPSBN);
        float cb = lbn2[64 + t] - lbn2[128 + t] * a;
        float v = a * acc + cb;
        sz2[t] = (v >= 0.f) ? v : 0.01f * v;
    }
    __syncthreads();
    if (t < CLSN) {
        float acc = lb3[t];
#pragma unroll
        for (int i = 0; i < 64; i++) acc += lw3[t * 64 + i] * sz2[i];
        out[b * CLSN + t] = acc;
    }
}

// ---------------- launch ----------------
extern "C" void kernel_launch(void* const* d_in, const int* in_sizes, int n_in,
                              void* d_out, int out_size) {
    const float* x    = (const float*)d_in[0];
    const float* w1   = (const float*)d_in[1];
    const float* bn1  = (const float*)d_in[2];
    const float* w2   = (const float*)d_in[3];
    const float* bn2  = (const float*)d_in[4];
    const float* w3   = (const float*)d_in[5];
    const float* bn3  = (const float*)d_in[6];
    const float* w4   = (const float*)d_in[7];
    const float* bn4  = (const float*)d_in[8];
    const float* w5   = (const float*)d_in[9];
    const float* bn5  = (const float*)d_in[10];
    const float* w6   = (const float*)d_in[11];
    const float* bn6  = (const float*)d_in[12];
    const float* lw1  = (const float*)d_in[13];
    const float* lb1  = (const float*)d_in[14];
    const float* lbn1 = (const float*)d_in[15];
    const float* lw2  = (const float*)d_in[16];
    const float* lb2  = (const float*)d_in[17];
    const float* lbn2 = (const float*)d_in[18];
    const float* lw3  = (const float*)d_in[19];
    const float* lb3  = (const float*)d_in[20];
    float* out = (float*)d_out;
    (void)in_sizes; (void)n_in; (void)out_size;

    dim3 knn_grid(NN / 32, BB);   // 64 x 8 = 512 blocks of 128 threads
    const int EG = 592;

    // stage 1 (input C=3); base inlined into edge -> knn64 is visible launch #4
    xx3t_kernel<<<(PTS + 255) / 256, 256>>>(x);
    knn3_kernel<<<knn_grid, 128>>>(x);
    edge_kernel<3, 0, 0, 1, 1><<<EG, 96>>>(0, w1, bn1, w5, 0, 0, nullptr);
    // stage 2
    knn64_kernel<<<knn_grid, 128>>>(0);          // <-- profiled slot (#4)
    base_kernel<64><<<PTS / 128, 128>>>(w2, 0);
    edge_kernel<64, 1, 0, 1, 0><<<EG, 96>>>(0, w2, bn2, w5, 64, 1, nullptr);
    // stage 3
    knn64_kernel<<<knn_grid, 128>>>(1);
    base_kernel<64><<<PTS / 128, 128>>>(w3, 1);
    edge_kernel<64, 1, 0, 1, 0><<<EG, 96>>>(1, w3, bn3, w5, 128, 0, nullptr);
    // stage 4 (fused bn5+lrelu+max_k)
    knn64_kernel<<<knn_grid, 128>>>(0);
    base_kernel<64><<<PTS / 128, 128>>>(w4, 0);
    edge_kernel<64, 1, 1, 0, 0><<<EG, 96>>>(0, w4, bn4, w5, 192, 1, bn5);
    // tail
    conv6_kernel<<<dim3(NN / 128, BB), 256>>>(w6, bn6);
    reduce2_kernel<<<BB, 256>>>();
    fc_kernel<<<BB, 256>>>(lw1, lb1, lbn1, lw2, lb2, lbn2, lw3, lb3, out);
}

// round 17
// speedup vs baseline: 1.2888x; 1.1008x over previous
#include <cuda_runtime.h>
#include <math.h>

#define BB   8
#define NN   2048
#define KNN  20
#define CLSN 40
#define EPSBN 1e-5f
#define PTS  (BB * NN)

typedef unsigned long long ull;

// ---------------- f32x2 packed-math helpers (sm_100a) ----------------
__device__ __forceinline__ ull splat2(float x) {
    unsigned u = __float_as_uint(x);
    ull r;
    asm("mov.b64 %0, {%1, %1};" : "=l"(r) : "r"(u));
    return r;
}
__device__ __forceinline__ ull pack2(float x, float y) {
    ull r;
    asm("mov.b64 %0, {%1, %2};" : "=l"(r) : "r"(__float_as_uint(x)), "r"(__float_as_uint(y)));
    return r;
}
__device__ __forceinline__ float2 unpack2(ull v) {
    unsigned lo, hi;
    asm("mov.b64 {%0, %1}, %2;" : "=r"(lo), "=r"(hi) : "l"(v));
    return make_float2(__uint_as_float(lo), __uint_as_float(hi));
}
__device__ __forceinline__ void ffma2(ull& acc, ull a, ull b) {
    asm("fma.rn.f32x2 %0, %1, %2, %0;" : "+l"(acc) : "l"(a), "l"(b));
}

// Exact order-preserving 64-bit key: high32 = monotone float bits (FULL precision),
// low32 = ~m  -> unique keys; equal values order by LOWER index first (= reference).
__device__ __forceinline__ ull packkey(float v, int m) {
    unsigned u = __float_as_uint(v);
    u ^= ((unsigned)((int)u >> 31)) | 0x80000000u;
    return ((ull)u << 32) | (ull)(0xFFFFFFFFu - (unsigned)m);
}

// ---------------- scratch (static __device__ — no allocations) ----------------
__device__ float g_xx[PTS];
__device__ float g_xt3[PTS * 3];
__device__ int   g_idx[PTS * KNN];
__device__ float g_feat[2][BB * 64 * NN];              // [c][n] layout (for knn)
__device__ float g_featt[2][(size_t)PTS * 64];         // [n][c] layout (for gather)
__device__ float g_base[PTS * 64];
__device__ float g_hacc[(size_t)PTS * KNN * 64];
__device__ float g_hm[BB * 64 * NN];
__device__ float g_pmax[BB * 16 * 256];
__device__ float g_psum[BB * 16 * 256];
__device__ float g_gvec[BB * 512];

// ---------------- stage-1 norms + transpose ----------------
__global__ void xx3t_kernel(const float* __restrict__ x) {
    int t = blockIdx.x * blockDim.x + threadIdx.x;
    if (t >= PTS) return;
    int b = t / NN, n = t % NN;
    float v0 = x[(b * 3 + 0) * NN + n];
    float v1 = x[(b * 3 + 1) * NN + n];
    float v2 = x[(b * 3 + 2) * NN + n];
    g_xx[t] = v0 * v0 + v1 * v1 + v2 * v2;
    g_xt3[t * 3 + 0] = v0;
    g_xt3[t * 3 + 1] = v1;
    g_xt3[t * 3 + 2] = v2;
}

// ---------------- top-k: EXACT register-resident bubble-carry insert ---------
struct TopK {
    float v[KNN];
    int   id[KNN];
    float thr;
    __device__ __forceinline__ void init() {
#pragma unroll
        for (int i = 0; i < KNN; i++) { v[i] = -3e38f; id[i] = 0; }
        thr = -3e38f;
    }
    __device__ __forceinline__ void push(float val, int m) {
        if (val > thr) {
            float cv = val; int ci = m;
#pragma unroll
            for (int i = 0; i < KNN; i++) {
                bool sw = (cv > v[i]);
                float nv = sw ? cv : v[i];
                int   ni = sw ? ci : id[i];
                cv = sw ? v[i] : cv;
                ci = sw ? id[i] : ci;
                v[i] = nv; id[i] = ni;
            }
            thr = v[KNN - 1];
        }
    }
};

// ---------------- 4-way merge of sorted packed-key lists (exact) -------------
__device__ __forceinline__ void merge4_to(const ull* L0, const ull* L1,
                                          const ull* L2, const ull* L3, int* op) {
    int p0 = 0, p1 = 0, p2 = 0, p3 = 0;
#pragma unroll
    for (int k = 0; k < KNN; k++) {
        ull a = L0[p0], b = L1[p1], c = L2[p2], d = L3[p3];
        ull best = a; int src = 0;
        if (b > best) { best = b; src = 1; }
        if (c > best) { best = c; src = 2; }
        if (d > best) { best = d; src = 3; }
        op[k] = (int)(0xFFFFFFFFu - (unsigned)(best & 0xFFFFFFFFull));
        if (src == 0) p0++; else if (src == 1) p1++; else if (src == 2) p2++; else p3++;
    }
}

// ---------------- kNN, C=3 (stage 1): 32 queries x 4 groups, buffered --------
__global__ __launch_bounds__(128) void knn3_kernel(const float* __restrict__ x) {
    __shared__ __align__(16) float sm[4][NN];  // 32KB tile; lists g1-3 overlay after
    __shared__ ull l0[32 * KNN];               // 5KB group-0 lists
    __shared__ float sbv[4][8][32];            // 4KB per-lane candidate buffers
    __shared__ int   sbi[4][8][32];            // 4KB
    int b = blockIdx.y;
    int tid = threadIdx.x;
    int q = tid & 31, g = tid >> 5;            // group == warp id (uniform)
    int n = blockIdx.x * 32 + q;
    for (int i = tid; i < NN; i += 128) {
        sm[0][i] = x[(b * 3 + 0) * NN + i];
        sm[1][i] = x[(b * 3 + 1) * NN + i];
        sm[2][i] = x[(b * 3 + 2) * NN + i];
        sm[3][i] = g_xx[b * NN + i];
    }
    __syncthreads();
    float q0 = sm[0][n], q1 = sm[1][n], q2 = sm[2][n], xq = sm[3][n];
    TopK tk; tk.init();
    int mbase = g * 512;
    int cnt = 0;
    for (int m = mbase; m < mbase + 512; m += 4) {
#pragma unroll
        for (int t = 0; t < 4; t++) {
            float d = q0 * sm[0][m + t] + q1 * sm[1][m + t] + q2 * sm[2][m + t];
            float val = 2.f * d - xq - sm[3][m + t];
            if (val > tk.thr) { sbv[g][cnt][q] = val; sbi[g][cnt][q] = m + t; cnt++; }
        }
        if (__ballot_sync(0xffffffffu, cnt >= 5)) {
#pragma unroll 1
            for (int i = 0; i < cnt; i++) tk.push(sbv[g][i][q], sbi[g][i][q]);
            cnt = 0;
        }
    }
#pragma unroll 1
    for (int i = 0; i < cnt; i++) tk.push(sbv[g][i][q], sbi[g][i][q]);
    __syncthreads();                            // all reads of sm done
    ull* lg = (g == 0) ? &l0[q * KNN] : ((ull*)sm) + ((g - 1) * 32 + q) * KNN;
#pragma unroll
    for (int k = 0; k < KNN; k++) lg[k] = packkey(tk.v[k], tk.id[k]);
    __syncthreads();
    if (tid < 32) {
        merge4_to(&l0[tid * KNN],
                  ((ull*)sm) + (0 * 32 + tid) * KNN,
                  ((ull*)sm) + (1 * 32 + tid) * KNN,
                  ((ull*)sm) + (2 * 32 + tid) * KNN,
                  g_idx + (b * NN + blockIdx.x * 32 + tid) * KNN);
    }
}

// ---------------- kNN, C=64: 32 queries x 4 groups, f32x2 + buffered ---------
__global__ __launch_bounds__(128) void knn64_kernel(int sel) {
    const float* x = g_feat[sel];               // [b][64][NN]
    __shared__ __align__(16) float4 s4[4 * 512]; // 32KB; per-group 32-cand tile
    __shared__ float sxx[4][32];
    __shared__ ull l0[32 * KNN];                // 5KB group-0 lists
    __shared__ float sbv[4][8][32];             // 4KB per-lane candidate buffers
    __shared__ int   sbi[4][8][32];             // 4KB
    int b = blockIdx.y;
    int tid = threadIdx.x;
    int q = tid & 31, g = tid >> 5;             // group == warp id (uniform)
    int n = blockIdx.x * 32 + q;
    float qf[64];
#pragma unroll
    for (int c = 0; c < 64; c++) qf[c] = x[(b * 64 + c) * NN + n];
    float xq = g_xx[b * NN + n];
    TopK tk; tk.init();
    int mbase = g * 512;
    float4* sg = s4 + g * 512;
    int cnt = 0;
    for (int m0 = 0; m0 < 512; m0 += 32) {
        __syncthreads();
        for (int i = q; i < 512; i += 32) {     // 512 float4 = 64 ch x 32 cands
            int c = i >> 3, j = i & 7;
            sg[i] = *(const float4*)&x[(b * 64 + c) * NN + mbase + m0 + j * 4];
        }
        sxx[g][q] = g_xx[b * NN + mbase + m0 + q];
        __syncthreads();
        for (int j8 = 0; j8 < 4; j8++) {        // 8 candidates per iteration
            ull d01 = 0, d23 = 0, d45 = 0, d67 = 0;
#pragma unroll
            for (int c = 0; c < 64; c++) {      // FULL unroll: qf stays in regs
                ull q2 = splat2(qf[c]);
                ulonglong2 va = *(const ulonglong2*)&sg[c * 8 + j8 * 2];
                ulonglong2 vb = *(const ulonglong2*)&sg[c * 8 + j8 * 2 + 1];
                ffma2(d01, q2, va.x); ffma2(d23, q2, va.y);
                ffma2(d45, q2, vb.x); ffma2(d67, q2, vb.y);
            }
            int m = mbase + m0 + j8 * 8;
            int jb = j8 * 8;
            float vals[8];
            float2 p;
            p = unpack2(d01);
            vals[0] = 2.f * p.x - xq - sxx[g][jb + 0];
            vals[1] = 2.f * p.y - xq - sxx[g][jb + 1];
            p = unpack2(d23);
            vals[2] = 2.f * p.x - xq - sxx[g][jb + 2];
            vals[3] = 2.f * p.y - xq - sxx[g][jb + 3];
            p = unpack2(d45);
            vals[4] = 2.f * p.x - xq - sxx[g][jb + 4];
            vals[5] = 2.f * p.y - xq - sxx[g][jb + 5];
            p = unpack2(d67);
            vals[6] = 2.f * p.x - xq - sxx[g][jb + 6];
            vals[7] = 2.f * p.y - xq - sxx[g][jb + 7];
#pragma unroll
            for (int t = 0; t < 8; t++) {
                if (vals[t] > tk.thr) { sbv[g][cnt][q] = vals[t]; sbi[g][cnt][q] = m + t; cnt++; }
                if ((t & 3) == 3) {
                    if (__ballot_sync(0xffffffffu, cnt >= 5)) {
#pragma unroll 1
                        for (int i = 0; i < cnt; i++) tk.push(sbv[g][i][q], sbi[g][i][q]);
                        cnt = 0;
                    }
                }
            }
        }
    }
#pragma unroll 1
    for (int i = 0; i < cnt; i++) tk.push(sbv[g][i][q], sbi[g][i][q]);
    __syncthreads();                            // all reads of s4 done
    ull* lg = (g == 0) ? &l0[q * KNN] : ((ull*)s4) + ((g - 1) * 32 + q) * KNN;
#pragma unroll
    for (int k = 0; k < KNN; k++) lg[k] = packkey(tk.v[k], tk.id[k]);
    __syncthreads();
    if (tid < 32) {
        merge4_to(&l0[tid * KNN],
                  ((ull*)s4) + (0 * 32 + tid) * KNN,
                  ((ull*)s4) + (1 * 32 + tid) * KNN,
                  ((ull*)s4) + (2 * 32 + tid) * KNN,
                  g_idx + (b * NN + blockIdx.x * 32 + tid) * KNN);
    }
}

// ---------------- base = (Wc - Wd) @ ctr  (C=64 stages only) -----------------
template <int C>
__global__ __launch_bounds__(128) void base_kernel(const float* __restrict__ w, int selt) {
    __shared__ float wcd[64 * C];
    const float* xt = (C == 3) ? g_xt3 : g_featt[selt];
    int tid = threadIdx.x;
    for (int i = tid; i < 64 * C; i += 128) {
        int o = i / C, c = i - o * C;
        wcd[i] = w[o * 2 * C + C + c] - w[o * 2 * C + c];
    }
    __syncthreads();
    int p = blockIdx.x * 128 + tid;
    float xr[C];
#pragma unroll
    for (int c = 0; c < C; c++) xr[c] = xt[(size_t)p * C + c];
#pragma unroll 4
    for (int o = 0; o < 64; o++) {
        float a = 0.f;
#pragma unroll
        for (int c = 0; c < C; c++) a += wcd[o * C + c] * xr[c];
        g_base[p * 64 + o] = a;
    }
}

// ---------------- EdgeConv + fused w5-slice accumulate, f32x2 GEMMs ----------
// B3: inline base computation for C=3 (removes the separate base3 launch).
template <int C, int ACCUM, int FINAL, int WRITEX, int B3>
__global__ __launch_bounds__(96) void edge_kernel(
    int selin,
    const float* __restrict__ w,    // [64][2C]
    const float* __restrict__ bnp,  // [4][64]
    const float* __restrict__ w5,   // [64][256]
    int w5off, int selout,
    const float* __restrict__ bnp5)
{
    __shared__ __align__(16) float sm[C * 64 + 4096 + 3 * 1280];
    __shared__ int sid[3][KNN];
    __shared__ float wcd3[3 * 64];   // (Wc-Wd) interleaved, used when B3
    const float* xin_t = (C == 3) ? g_xt3 : g_featt[selin];
    float* xout  = g_feat[selout];
    float* xoutt = g_featt[selout];
    float* wd2 = sm;                 // [C][64]: (Wd[j][c], Wd[j+32][c])
    float* w52 = sm + C * 64;        // [64][64]: (w5[j][off+o], w5[j+32][off+o])
    int tid = threadIdx.x;
    float* wbuf = sm + C * 64 + 4096 + (tid >> 5) * 1280;

    for (int i = tid; i < C * 64; i += 96) {
        int c = i >> 6, t2 = i & 63, jj = t2 >> 1, hi = t2 & 1;
        wd2[i] = w[(jj + 32 * hi) * (2 * C) + c];
    }
    if (B3) {
        for (int i = tid; i < 3 * 64; i += 96) {
            int c = i >> 6, t2 = i & 63, jj = t2 >> 1, hi = t2 & 1;
            int o = jj + 32 * hi;
            wcd3[i] = w[o * 6 + 3 + c] - w[o * 6 + c];
        }
    }
    for (int i = tid; i < 4096; i += 96) {
        int o = i >> 6, t2 = i & 63, jj = t2 >> 1, hi = t2 & 1;
        w52[i] = w5[(jj + 32 * hi) * 256 + w5off + o];
    }
    __syncthreads();

    int lane = tid & 31, warp = tid >> 5;
    int* myid = sid[warp];
    float a0 = bnp[lane] * rsqrtf(bnp[192 + lane] + EPSBN);
    float c0 = bnp[64 + lane] - bnp[128 + lane] * a0;
    float a1 = bnp[32 + lane] * rsqrtf(bnp[224 + lane] + EPSBN);
    float c1 = bnp[96 + lane] - bnp[160 + lane] * a1;
    float a5l = 0.f, c5l = 0.f, a5h = 0.f, c5h = 0.f;
    if (FINAL) {
        a5l = bnp5[lane] * rsqrtf(bnp5[192 + lane] + EPSBN);
        c5l = bnp5[64 + lane] - bnp5[128 + lane] * a5l;
        a5h = bnp5[32 + lane] * rsqrtf(bnp5[224 + lane] + EPSBN);
        c5h = bnp5[96 + lane] - bnp5[160 + lane] * a5h;
    }

    for (int p = blockIdx.x * 3 + warp; p < PTS; p += gridDim.x * 3) {
        int b = p >> 11, n = p & (NN - 1);
        if (lane < KNN) myid[lane] = g_idx[p * KNN + lane];
        __syncwarp();
        if (C == 64) {
#pragma unroll
            for (int i = 0; i < 10; i++) {
                int idx = lane + i * 32;
                int k = idx >> 4, c4 = idx & 15;
                int nb = myid[k];
                float4 v = *(const float4*)&xin_t[((size_t)b * NN + nb) * 64 + c4 * 4];
                wbuf[(c4 * 4 + 0) * KNN + k] = v.x;
                wbuf[(c4 * 4 + 1) * KNN + k] = v.y;
                wbuf[(c4 * 4 + 2) * KNN + k] = v.z;
                wbuf[(c4 * 4 + 3) * KNN + k] = v.w;
            }
        } else {
            for (int t = lane; t < C * KNN; t += 32) {
                int k = t / C, c = t - k * C;
                wbuf[c * KNN + k] = xin_t[((size_t)b * NN + myid[k]) * C + c];
            }
        }
        __syncwarp();
        float base0, base1;
        if (B3 && C == 3) {
            float x0 = g_xt3[p * 3 + 0];
            float x1 = g_xt3[p * 3 + 1];
            float x2 = g_xt3[p * 3 + 2];
            float t0 = 0.f, t1 = 0.f;
            t0 += wcd3[0 * 64 + 2 * lane] * x0;
            t0 += wcd3[1 * 64 + 2 * lane] * x1;
            t0 += wcd3[2 * 64 + 2 * lane] * x2;
            t1 += wcd3[0 * 64 + 2 * lane + 1] * x0;
            t1 += wcd3[1 * 64 + 2 * lane + 1] * x1;
            t1 += wcd3[2 * 64 + 2 * lane + 1] * x2;
            base0 = t0; base1 = t1;
        } else {
            base0 = g_base[p * 64 + lane];
            base1 = g_base[p * 64 + 32 + lane];
        }
        ull acc0p[10], acc1p[10];
        {
            ull b0 = splat2(base0);
            ull b1 = splat2(base1);
#pragma unroll
            for (int i = 0; i < 10; i++) { acc0p[i] = b0; acc1p[i] = b1; }
        }
#pragma unroll 8
        for (int c = 0; c < C; c++) {
            float2 wv = *(const float2*)&wd2[c * 64 + 2 * lane];
            ull wx = splat2(wv.x), wy = splat2(wv.y);
            const ulonglong2* nb2 = (const ulonglong2*)&wbuf[c * KNN];
#pragma unroll
            for (int qd = 0; qd < 5; qd++) {
                ulonglong2 v = nb2[qd];
                ffma2(acc0p[2 * qd], wx, v.x); ffma2(acc0p[2 * qd + 1], wx, v.y);
                ffma2(acc1p[2 * qd], wy, v.x); ffma2(acc1p[2 * qd + 1], wy, v.y);
            }
        }
        __syncwarp();
        float ym0 = -3e38f, ym1 = -3e38f;
#pragma unroll
        for (int i = 0; i < 10; i++) {
            float2 u0 = unpack2(acc0p[i]);
            float2 u1 = unpack2(acc1p[i]);
            float y00 = a0 * u0.x + c0; y00 = (y00 >= 0.f) ? y00 : 0.2f * y00;
            float y01 = a0 * u0.y + c0; y01 = (y01 >= 0.f) ? y01 : 0.2f * y01;
            float y10 = a1 * u1.x + c1; y10 = (y10 >= 0.f) ? y10 : 0.2f * y10;
            float y11 = a1 * u1.y + c1; y11 = (y11 >= 0.f) ? y11 : 0.2f * y11;
            ym0 = fmaxf(ym0, fmaxf(y00, y01));
            ym1 = fmaxf(ym1, fmaxf(y10, y11));
            *(ull*)&wbuf[lane * KNN + 2 * i]        = pack2(y00, y01);
            *(ull*)&wbuf[(lane + 32) * KNN + 2 * i] = pack2(y10, y11);
        }
        __syncwarp();
        ull h0p[10], h1p[10];
#pragma unroll
        for (int i = 0; i < 10; i++) { h0p[i] = 0ull; h1p[i] = 0ull; }
#pragma unroll 8
        for (int o = 0; o < 64; o++) {
            float2 wv = *(const float2*)&w52[o * 64 + 2 * lane];
            ull wx = splat2(wv.x), wy = splat2(wv.y);
            const ulonglong2* y2 = (const ulonglong2*)&wbuf[o * KNN];
#pragma unroll
            for (int qd = 0; qd < 5; qd++) {
                ulonglong2 v = y2[qd];
                ffma2(h0p[2 * qd], wx, v.x); ffma2(h0p[2 * qd + 1], wx, v.y);
                ffma2(h1p[2 * qd], wy, v.x); ffma2(h1p[2 * qd + 1], wy, v.y);
            }
        }
        float* hp = g_hacc + (size_t)p * KNN * 64;
        if (FINAL) {
            float m0 = -3e38f, m1 = -3e38f;
#pragma unroll
            for (int i = 0; i < 10; i++) {
                float2 h0 = unpack2(h0p[i]);
                float2 h1 = unpack2(h1p[i]);
                float v00 = a5l * (hp[(2 * i) * 64 + lane] + h0.x) + c5l;
                v00 = (v00 >= 0.f) ? v00 : 0.2f * v00;
                float v01 = a5l * (hp[(2 * i + 1) * 64 + lane] + h0.y) + c5l;
                v01 = (v01 >= 0.f) ? v01 : 0.2f * v01;
                float v10 = a5h * (hp[(2 * i) * 64 + 32 + lane] + h1.x) + c5h;
                v10 = (v10 >= 0.f) ? v10 : 0.2f * v10;
                float v11 = a5h * (hp[(2 * i + 1) * 64 + 32 + lane] + h1.y) + c5h;
                v11 = (v11 >= 0.f) ? v11 : 0.2f * v11;
                m0 = fmaxf(m0, fmaxf(v00, v01));
                m1 = fmaxf(m1, fmaxf(v10, v11));
            }
            g_hm[(b * 64 + lane) * NN + n]      = m0;
            g_hm[(b * 64 + 32 + lane) * NN + n] = m1;
        } else if (ACCUM) {
#pragma unroll
            for (int i = 0; i < 10; i++) {
                float2 h0 = unpack2(h0p[i]);
                float2 h1 = unpack2(h1p[i]);
                hp[(2 * i) * 64 + lane]          += h0.x;
                hp[(2 * i + 1) * 64 + lane]      += h0.y;
                hp[(2 * i) * 64 + 32 + lane]     += h1.x;
                hp[(2 * i + 1) * 64 + 32 + lane] += h1.y;
            }
        } else {
#pragma unroll
            for (int i = 0; i < 10; i++) {
                float2 h0 = unpack2(h0p[i]);
                float2 h1 = unpack2(h1p[i]);
                hp[(2 * i) * 64 + lane]          = h0.x;
                hp[(2 * i + 1) * 64 + lane]      = h0.y;
                hp[(2 * i) * 64 + 32 + lane]     = h1.x;
                hp[(2 * i + 1) * 64 + 32 + lane] = h1.y;
            }
        }
        if (WRITEX) {
            xout[(b * 64 + lane) * NN + n]      = ym0;
            xout[(b * 64 + 32 + lane) * NN + n] = ym1;
            xoutt[((size_t)b * NN + n) * 64 + lane]      = ym0;
            xoutt[((size_t)b * NN + n) * 64 + 32 + lane] = ym1;
            float xxv = ym0 * ym0 + ym1 * ym1;
#pragma unroll
            for (int off = 16; off > 0; off >>= 1)
                xxv += __shfl_xor_sync(0xffffffffu, xxv, off);
            if (lane == 0) g_xx[p] = xxv;
        }
        __syncwarp();
    }
}

// ---------------- conv6 (64 -> 256) + bn6 + lrelu + fused tile reduce --------
__global__ __launch_bounds__(256) void conv6_kernel(const float* __restrict__ w6,
                                                    const float* __restrict__ bnp) {
    __shared__ float sh[64 * 128];
    int b = blockIdx.y, tile = blockIdx.x, n0 = tile * 128;
    for (int i = threadIdx.x; i < 64 * 128; i += 256) {
        int c = i >> 7, j = i & 127;
        sh[i] = g_hm[(b * 64 + c) * NN + n0 + j];
    }
    int o2 = threadIdx.x;
    float wr[64];
#pragma unroll
    for (int o = 0; o < 64; o++) wr[o] = w6[o2 * 64 + o];
    float a = bnp[o2] * rsqrtf(bnp[768 + o2] + EPSBN);
    float cb = bnp[256 + o2] - bnp[512 + o2] * a;
    __syncthreads();
    float m = -3e38f, sum = 0.f;
    for (int jj = 0; jj < 64; jj++) {
        float s0 = 0.f, s1 = 0.f;
#pragma unroll
        for (int o = 0; o < 64; o++) {
            float2 v = *(const float2*)&sh[o * 128 + jj * 2];
            s0 += wr[o] * v.x;
            s1 += wr[o] * v.y;
        }
        float v0 = a * s0 + cb; v0 = (v0 >= 0.f) ? v0 : 0.2f * v0;
        float v1 = a * s1 + cb; v1 = (v1 >= 0.f) ? v1 : 0.2f * v1;
        m = fmaxf(m, fmaxf(v0, v1));
        sum += v0;
        sum += v1;
    }
    g_pmax[(b * 16 + tile) * 256 + o2] = m;
    g_psum[(b * 16 + tile) * 256 + o2] = sum;
}

// ---------------- final global max + mean over tiles ----------------
__global__ void reduce2_kernel() {
    int b = blockIdx.x, o = threadIdx.x;
    float m = -3e38f, s = 0.f;
#pragma unroll
    for (int j = 0; j < 16; j++) {
        m = fmaxf(m, g_pmax[(b * 16 + j) * 256 + o]);
        s += g_psum[(b * 16 + j) * 256 + o];
    }
    g_gvec[b * 512 + o] = m;
    g_gvec[b * 512 + 256 + o] = s * (1.0f / NN);
}

// ---------------- FC head ----------------
__global__ __launch_bounds__(256) void fc_kernel(
    const float* __restrict__ lw1, const float* __restrict__ lb1, const float* __restrict__ lbn1,
    const float* __restrict__ lw2, const float* __restrict__ lb2, const float* __restrict__ lbn2,
    const float* __restrict__ lw3, const float* __restrict__ lb3, float* __restrict__ out) {
    __shared__ float sg[512];
    __shared__ float sz[256];
    __shared__ float sz2[64];
    int b = blockIdx.x, t = threadIdx.x;
    sg[t] = g_gvec[b * 512 + t];
    sg[t + 256] = g_gvec[b * 512 + 256 + t];
    __syncthreads();
    {
        float acc = lb1[t];
#pragma unroll 8
        for (int i = 0; i < 512; i++) acc += lw1[t * 512 + i] * sg[i];
        float a = lbn1[t] * rsqrtf(lbn1[768 + t] + EPSBN);
        float cb = lbn1[256 + t] - lbn1[512 + t] * a;
        float v = a * acc + cb;
        sz[t] = (v >= 0.f) ? v : 0.01f * v;
    }
    __syncthreads();
    if (t < 64) {
        float acc = lb2[t];
#pragma unroll 8
        for (int i = 0; i < 256; i++) acc += lw2[t * 256 + i] * sz[i];
        float a = lbn2[t] * rsqrtf(lbn2[192 + t] + EPSBN);
        float cb = lbn2[64 + t] - lbn2[128 + t] * a;
        float v = a * acc + cb;
        sz2[t] = (v >= 0.f) ? v : 0.01f * v;
    }
    __syncthreads();
    if (t < CLSN) {
        float acc = lb3[t];
#pragma unroll
        for (int i = 0; i < 64; i++) acc += lw3[t * 64 + i] * sz2[i];
        out[b * CLSN + t] = acc;
    }
}

// ---------------- launch ----------------
extern "C" void kernel_launch(void* const* d_in, const int* in_sizes, int n_in,
                              void* d_out, int out_size) {
    const float* x    = (const float*)d_in[0];
    const float* w1   = (const float*)d_in[1];
    const float* bn1  = (const float*)d_in[2];
    const float* w2   = (const float*)d_in[3];
    const float* bn2  = (const float*)d_in[4];
    const float* w3   = (const float*)d_in[5];
    const float* bn3  = (const float*)d_in[6];
    const float* w4   = (const float*)d_in[7];
    const float* bn4  = (const float*)d_in[8];
    const float* w5   = (const float*)d_in[9];
    const float* bn5  = (const float*)d_in[10];
    const float* w6   = (const float*)d_in[11];
    const float* bn6  = (const float*)d_in[12];
    const float* lw1  = (const float*)d_in[13];
    const float* lb1  = (const float*)d_in[14];
    const float* lbn1 = (const float*)d_in[15];
    const float* lw2  = (const float*)d_in[16];
    const float* lb2  = (const float*)d_in[17];
    const float* lbn2 = (const float*)d_in[18];
    const float* lw3  = (const float*)d_in[19];
    const float* lb3  = (const float*)d_in[20];
    float* out = (float*)d_out;
    (void)in_sizes; (void)n_in; (void)out_size;

    dim3 knn_grid(NN / 32, BB);   // 64 x 8 = 512 blocks of 128 threads
    const int EG = 592;

    // stage 1 (input C=3); knn64 stays visible launch #4 for profiling
    xx3t_kernel<<<(PTS + 255) / 256, 256>>>(x);
    knn3_kernel<<<knn_grid, 128>>>(x);
    edge_kernel<3, 0, 0, 1, 1><<<EG, 96>>>(0, w1, bn1, w5, 0, 0, nullptr);
    // stage 2
    knn64_kernel<<<knn_grid, 128>>>(0);          // <-- profiled slot (#4)
    base_kernel<64><<<PTS / 128, 128>>>(w2, 0);
    edge_kernel<64, 1, 0, 1, 0><<<EG, 96>>>(0, w2, bn2, w5, 64, 1, nullptr);
    // stage 3
    knn64_kernel<<<knn_grid, 128>>>(1);
    base_kernel<64><<<PTS / 128, 128>>>(w3, 1);
    edge_kernel<64, 1, 0, 1, 0><<<EG, 96>>>(1, w3, bn3, w5, 128, 0, nullptr);
    // stage 4 (fused bn5+lrelu+max_k)
    knn64_kernel<<<knn_grid, 128>>>(0);
    base_kernel<64><<<PTS / 128, 128>>>(w4, 0);
    edge_kernel<64, 1, 1, 0, 0><<<EG, 96>>>(0, w4, bn4, w5, 192, 1, bn5);
    // tail
    conv6_kernel<<<dim3(NN / 128, BB), 256>>>(w6, bn6);
    reduce2_kernel<<<BB, 256>>>();
    fc_kernel<<<BB, 256>>>(lw1, lb1, lbn1, lw2, lb2, lbn2, lw3, lb3, out);
}